// round 3
// baseline (speedup 1.0000x reference)
#include <cuda_runtime.h>
#include <cstdint>

// ---------------- problem constants (fixed by the dataset) ----------------
#define IN_C   128
#define LEAF   50000
#define N0_MAX 100000
#define W_BAG  16
#define N1_C   25000
#define N2_C   5000

// ---------------- device scratch (allocation-free rule) -------------------
__device__ float g_h0[(size_t)N0_MAX * IN_C];     // 51.2 MB  embed+LN+relu
__device__ float g_h1[(size_t)N1_C * IN_C];       // 12.8 MB  sage1 output (relu'd)
__device__ float g_agg1[(size_t)N1_C * IN_C];     // 12.8 MB
__device__ float g_agg2[(size_t)N2_C * IN_C];     //  2.6 MB
__device__ int   g_cnt1[N1_C];
__device__ int   g_cnt2[N2_C];
__device__ float g_Wt1[256 * 128];                // [k][t] combined (Wl|Wr) transposed
__device__ float g_Wt2[256 * 128];

// ---------------- zero the per-call accumulators ---------------------------
__global__ void zero_scratch() {
    int i  = blockIdx.x * blockDim.x + threadIdx.x;
    int st = gridDim.x * blockDim.x;
    for (int j = i; j < N1_C * IN_C; j += st) g_agg1[j] = 0.f;
    for (int j = i; j < N2_C * IN_C; j += st) g_agg2[j] = 0.f;
    for (int j = i; j < N1_C; j += st) g_cnt1[j] = 0;
    for (int j = i; j < N2_C; j += st) g_cnt2[j] = 0;
}

// ---------------- weight transpose: Wt[k][t] = k<128 ? Wl[t][k] : Wr[t][k-128]
__global__ void prep_weights(const float* __restrict__ Wl1, const float* __restrict__ Wr1,
                             const float* __restrict__ Wl2, const float* __restrict__ Wr2) {
    int i = blockIdx.x * blockDim.x + threadIdx.x;   // 0 .. 32767
    if (i >= 256 * 128) return;
    int k = i >> 7;
    int t = i & 127;
    g_Wt1[i] = (k < 128) ? Wl1[t * 128 + k] : Wr1[t * 128 + (k - 128)];
    g_Wt2[i] = (k < 128) ? Wl2[t * 128 + k] : Wr2[t * 128 + (k - 128)];
}

// ---------------- embedding bag sum + layernorm + relu ---------------------
// one warp handles 4 rows; lane c owns channels 4c..4c+3 (float4)
__global__ void embed_ln_relu(const int* __restrict__ x, const float* __restrict__ emb,
                              const float* __restrict__ g, const float* __restrict__ b,
                              int N0) {
    int warp = (blockIdx.x * blockDim.x + threadIdx.x) >> 5;
    int lane = threadIdx.x & 31;
    float4 gg = *(const float4*)(g + lane * 4);
    float4 bb = *(const float4*)(b + lane * 4);
    int row0 = warp * 4;
#pragma unroll
    for (int rr = 0; rr < 4; ++rr) {
        int row = row0 + rr;
        if (row >= N0) return;
        const int* xr = x + (size_t)row * W_BAG;
        float4 acc = make_float4(0.f, 0.f, 0.f, 0.f);
#pragma unroll
        for (int w = 0; w < W_BAG; ++w) {
            int idx = __ldg(xr + w);
            float4 e = *(const float4*)(emb + (size_t)idx * IN_C + lane * 4);
            acc.x += e.x; acc.y += e.y; acc.z += e.z; acc.w += e.w;
        }
        float s = acc.x + acc.y + acc.z + acc.w;
#pragma unroll
        for (int o = 16; o; o >>= 1) s += __shfl_xor_sync(0xffffffffu, s, o);
        float mu = s * (1.0f / 128.0f);
        float d0 = acc.x - mu, d1 = acc.y - mu, d2 = acc.z - mu, d3 = acc.w - mu;
        float q = d0 * d0 + d1 * d1 + d2 * d2 + d3 * d3;
#pragma unroll
        for (int o = 16; o; o >>= 1) q += __shfl_xor_sync(0xffffffffu, q, o);
        float rs = rsqrtf(q * (1.0f / 128.0f) + 1e-5f);
        float4 o4;
        o4.x = fmaxf(fmaf(d0 * rs, gg.x, bb.x), 0.f);
        o4.y = fmaxf(fmaf(d1 * rs, gg.y, bb.y), 0.f);
        o4.z = fmaxf(fmaf(d2 * rs, gg.z, bb.z), 0.f);
        o4.w = fmaxf(fmaf(d3 * rs, gg.w, bb.w), 0.f);
        *(float4*)(g_h0 + (size_t)row * IN_C + lane * 4) = o4;
    }
}

// ---------------- edge scatter-add (mean numerator + counts) ---------------
// one warp per edge: lane c handles channels 4c..4c+3 with a v4 global red.
__global__ void scatter_edges(const float* __restrict__ h, const int* __restrict__ src,
                              const int* __restrict__ dst, float* __restrict__ agg,
                              int* __restrict__ cnt, int E) {
    int e = blockIdx.x * (blockDim.x >> 5) + (threadIdx.x >> 5);
    if (e >= E) return;
    int lane = threadIdx.x & 31;
    int s = __ldg(src + e);
    int d = __ldg(dst + e);
    float4 v = *(const float4*)(h + (size_t)s * IN_C + lane * 4);
    float* p = agg + (size_t)d * IN_C + lane * 4;
    asm volatile("red.global.add.v4.f32 [%0], {%1,%2,%3,%4};"
                 :: "l"(p), "f"(v.x), "f"(v.y), "f"(v.z), "f"(v.w)
                 : "memory");
    if (lane == 0) atomicAdd(cnt + d, 1);
}

// ---------------- fused SAGE GEMM: out = mean@Wl^T + bl + self@Wr^T (+relu)
// A = [mean | self] is [n, 256]; Wt is [256, 128] ([k][t]).
// Tile: 64 rows x 128 cols per block, 256 threads, 4x8 register blocking.
__global__ __launch_bounds__(256, 4)
void sage_gemm(const float* __restrict__ agg, const int* __restrict__ cnt,
               const float* __restrict__ selfh, const float* __restrict__ Wt,
               const float* __restrict__ bias, float* __restrict__ out,
               int n, int do_relu) {
    __shared__ float  As[64][33];
    __shared__ float4 Ws4[32][32];   // [kk][c/4]
    __shared__ float  rinv[64];
    __shared__ float  bs[128];

    int tid  = threadIdx.x;
    int row0 = blockIdx.x * 64;
    int tx = tid & 15;       // col group (8 cols)
    int ty = tid >> 4;       // row group (4 rows)

    if (tid < 64) {
        int r = row0 + tid;
        rinv[tid] = (r < n) ? (1.0f / fmaxf((float)__ldg(cnt + r), 1.0f)) : 0.0f;
    }
    if (tid < 128) bs[tid] = bias[tid];

    float acc[4][8];
#pragma unroll
    for (int r = 0; r < 4; ++r)
#pragma unroll
        for (int c = 0; c < 8; ++c) acc[r][c] = 0.f;

    for (int kb = 0; kb < 256; kb += 32) {
        __syncthreads();
        // load A tile: warp -> one row slice of 32 consecutive k (coalesced)
        {
            int kk = tid & 31;
            int k  = kb + kk;
            for (int rr = tid >> 5; rr < 64; rr += 8) {
                int r = row0 + rr;
                float v = 0.f;
                if (r < n) {
                    if (k < 128) v = agg[(size_t)r * 128 + k] * rinv[rr];
                    else         v = selfh[(size_t)r * 128 + (k - 128)];
                }
                As[rr][kk] = v;
            }
        }
        // load W tile (float4, coalesced)
        for (int i = tid; i < 1024; i += 256) {
            int kk = i >> 5, c4 = i & 31;
            Ws4[kk][c4] = *(const float4*)(Wt + (size_t)(kb + kk) * 128 + c4 * 4);
        }
        __syncthreads();
#pragma unroll
        for (int kk = 0; kk < 32; ++kk) {
            float a0 = As[ty * 4 + 0][kk];
            float a1 = As[ty * 4 + 1][kk];
            float a2 = As[ty * 4 + 2][kk];
            float a3 = As[ty * 4 + 3][kk];
            float4 w0 = Ws4[kk][tx * 2 + 0];
            float4 w1 = Ws4[kk][tx * 2 + 1];
            float w[8] = {w0.x, w0.y, w0.z, w0.w, w1.x, w1.y, w1.z, w1.w};
#pragma unroll
            for (int c = 0; c < 8; ++c) {
                acc[0][c] = fmaf(a0, w[c], acc[0][c]);
                acc[1][c] = fmaf(a1, w[c], acc[1][c]);
                acc[2][c] = fmaf(a2, w[c], acc[2][c]);
                acc[3][c] = fmaf(a3, w[c], acc[3][c]);
            }
        }
    }

    // epilogue: bias (+relu), vectorized store
    int colb = tx * 8;
#pragma unroll
    for (int r = 0; r < 4; ++r) {
        int row = row0 + ty * 4 + r;
        if (row >= n) continue;
        float4 o0, o1;
        o0.x = acc[r][0] + bs[colb + 0];
        o0.y = acc[r][1] + bs[colb + 1];
        o0.z = acc[r][2] + bs[colb + 2];
        o0.w = acc[r][3] + bs[colb + 3];
        o1.x = acc[r][4] + bs[colb + 4];
        o1.y = acc[r][5] + bs[colb + 5];
        o1.z = acc[r][6] + bs[colb + 6];
        o1.w = acc[r][7] + bs[colb + 7];
        if (do_relu) {
            o0.x = fmaxf(o0.x, 0.f); o0.y = fmaxf(o0.y, 0.f);
            o0.z = fmaxf(o0.z, 0.f); o0.w = fmaxf(o0.w, 0.f);
            o1.x = fmaxf(o1.x, 0.f); o1.y = fmaxf(o1.y, 0.f);
            o1.z = fmaxf(o1.z, 0.f); o1.w = fmaxf(o1.w, 0.f);
        }
        *(float4*)(out + (size_t)row * 128 + colb)     = o0;
        *(float4*)(out + (size_t)row * 128 + colb + 4) = o1;
    }
}

// ---------------- host launcher --------------------------------------------
extern "C" void kernel_launch(void* const* d_in, const int* in_sizes, int n_in,
                              void* d_out, int out_size) {
    // input index layout: tolerate scalar inputs (n1, n2) present or absent
    int ix = 0, is1 = 1, id1 = 2, is2 = 3, id2 = 4;
    int iemb, ig, ib, iwl1, ibl1, iwr1, iwl2, ibl2, iwr2;
    if (n_in >= 16) {
        iemb = 7; ig = 8; ib = 9; iwl1 = 10; ibl1 = 11; iwr1 = 12;
        iwl2 = 13; ibl2 = 14; iwr2 = 15;
    } else {
        iemb = 5; ig = 6; ib = 7; iwl1 = 8; ibl1 = 9; iwr1 = 10;
        iwl2 = 11; ibl2 = 12; iwr2 = 13;
    }

    const int*   x    = (const int*)d_in[ix];
    const int*   src1 = (const int*)d_in[is1];
    const int*   dst1 = (const int*)d_in[id1];
    const int*   src2 = (const int*)d_in[is2];
    const int*   dst2 = (const int*)d_in[id2];
    const float* emb  = (const float*)d_in[iemb];
    const float* ln_g = (const float*)d_in[ig];
    const float* ln_b = (const float*)d_in[ib];
    const float* Wl1  = (const float*)d_in[iwl1];
    const float* bl1  = (const float*)d_in[ibl1];
    const float* Wr1  = (const float*)d_in[iwr1];
    const float* Wl2  = (const float*)d_in[iwl2];
    const float* bl2  = (const float*)d_in[ibl2];
    const float* Wr2  = (const float*)d_in[iwr2];

    int N0 = in_sizes[ix] / W_BAG;
    int E1 = in_sizes[is1];
    int E2 = in_sizes[is2];

    // resolve device-scratch addresses (no allocation; just symbol lookup)
    float *h0, *h1, *agg1, *agg2, *wt1, *wt2;
    int *cnt1, *cnt2;
    cudaGetSymbolAddress((void**)&h0,   g_h0);
    cudaGetSymbolAddress((void**)&h1,   g_h1);
    cudaGetSymbolAddress((void**)&agg1, g_agg1);
    cudaGetSymbolAddress((void**)&agg2, g_agg2);
    cudaGetSymbolAddress((void**)&cnt1, g_cnt1);
    cudaGetSymbolAddress((void**)&cnt2, g_cnt2);
    cudaGetSymbolAddress((void**)&wt1,  g_Wt1);
    cudaGetSymbolAddress((void**)&wt2,  g_Wt2);

    // 1. zero accumulators + 2. weight transpose (independent, both cheap)
    zero_scratch<<<1024, 256>>>();
    prep_weights<<<(256 * 128 + 255) / 256, 256>>>(Wl1, Wr1, Wl2, Wr2);

    // 3. embedding bag + LN + relu -> h0
    embed_ln_relu<<<(N0 + 31) / 32, 256>>>(x, emb, ln_g, ln_b, N0);

    // 4. layer-1 aggregation (atomics)
    scatter_edges<<<(E1 + 7) / 8, 256>>>(h0, src1, dst1, agg1, cnt1, E1);

    // 5. layer-1 fused GEMM + relu -> h1
    sage_gemm<<<(N1_C + 63) / 64, 256>>>(agg1, cnt1, h0, wt1, bl1, h1, N1_C, 1);

    // 6. layer-2 aggregation
    scatter_edges<<<(E2 + 7) / 8, 256>>>(h1, src2, dst2, agg2, cnt2, E2);

    // 7. layer-2 fused GEMM -> d_out
    sage_gemm<<<(N2_C + 63) / 64, 256>>>(agg2, cnt2, h1, wt2, bl2, (float*)d_out,
                                         N2_C, 0);
}

// round 4
// speedup vs baseline: 1.0973x; 1.0973x over previous
#include <cuda_runtime.h>
#include <cstdint>

// ---------------- problem constants (fixed by the dataset) ----------------
#define IN_C   128
#define LEAF   50000
#define N0_MAX 100000
#define W_BAG  16
#define N1_C   25000
#define N2_C   5000

typedef unsigned long long u64;

// ---------------- device scratch (allocation-free rule) -------------------
__device__ float g_h0[(size_t)N0_MAX * IN_C];     // 51.2 MB  embed+LN+relu
__device__ float g_h1[(size_t)N1_C * IN_C];       // 12.8 MB  sage1 output (relu'd)
__device__ float g_agg1[(size_t)N1_C * IN_C];     // 12.8 MB
__device__ float g_agg2[(size_t)N2_C * IN_C];     //  2.6 MB
__device__ int   g_cnt1[N1_C];
__device__ int   g_cnt2[N2_C];
__device__ float g_Wt1[256 * 128];                // [k][t] combined (Wl|Wr) transposed
__device__ float g_Wt2[256 * 128];

// ---------------- f32x2 packed-FMA helpers ---------------------------------
__device__ __forceinline__ u64 pack2(float a) {
    u64 r;
    unsigned ai = __float_as_uint(a);
    asm("mov.b64 %0, {%1, %1};" : "=l"(r) : "r"(ai));
    return r;
}
__device__ __forceinline__ void fma2(u64& d, u64 a, u64 b) {
    asm("fma.rn.f32x2 %0, %1, %2, %0;" : "+l"(d) : "l"(a), "l"(b));
}
__device__ __forceinline__ void unpack2(u64 v, float& lo, float& hi) {
    unsigned l, h;
    asm("mov.b64 {%0, %1}, %2;" : "=r"(l), "=r"(h) : "l"(v));
    lo = __uint_as_float(l);
    hi = __uint_as_float(h);
}

// ---------------- zero accumulators + weight transpose (one launch) --------
__global__ void init_scratch(const float* __restrict__ Wl1, const float* __restrict__ Wr1,
                             const float* __restrict__ Wl2, const float* __restrict__ Wr2) {
    int i  = blockIdx.x * blockDim.x + threadIdx.x;
    int st = gridDim.x * blockDim.x;
    for (int j = i; j < N1_C * IN_C; j += st) g_agg1[j] = 0.f;
    for (int j = i; j < N2_C * IN_C; j += st) g_agg2[j] = 0.f;
    for (int j = i; j < N1_C; j += st) g_cnt1[j] = 0;
    for (int j = i; j < N2_C; j += st) g_cnt2[j] = 0;
    for (int j = i; j < 256 * 128; j += st) {
        int k = j >> 7;
        int t = j & 127;
        g_Wt1[j] = (k < 128) ? Wl1[t * 128 + k] : Wr1[t * 128 + (k - 128)];
        g_Wt2[j] = (k < 128) ? Wl2[t * 128 + k] : Wr2[t * 128 + (k - 128)];
    }
}

// ---------------- embedding bag sum + layernorm + relu ---------------------
// one warp per row; bag indices loaded once (lane-distributed) and broadcast
// via shfl; all 16 gather loads independent -> MLP 16.
__global__ void embed_ln_relu(const int* __restrict__ x, const float* __restrict__ emb,
                              const float* __restrict__ g, const float* __restrict__ b,
                              int N0) {
    int warp = (blockIdx.x * blockDim.x + threadIdx.x) >> 5;
    int lane = threadIdx.x & 31;
    if (warp >= N0) return;

    int idx_l = (lane < W_BAG) ? __ldg(x + (size_t)warp * W_BAG + lane) : 0;

    float4 a0 = make_float4(0.f, 0.f, 0.f, 0.f);
    float4 a1 = make_float4(0.f, 0.f, 0.f, 0.f);
#pragma unroll
    for (int w = 0; w < W_BAG; w += 2) {
        int i0 = __shfl_sync(0xffffffffu, idx_l, w);
        int i1 = __shfl_sync(0xffffffffu, idx_l, w + 1);
        float4 e0 = __ldg((const float4*)(emb + (size_t)i0 * IN_C + lane * 4));
        float4 e1 = __ldg((const float4*)(emb + (size_t)i1 * IN_C + lane * 4));
        a0.x += e0.x; a0.y += e0.y; a0.z += e0.z; a0.w += e0.w;
        a1.x += e1.x; a1.y += e1.y; a1.z += e1.z; a1.w += e1.w;
    }
    float4 acc;
    acc.x = a0.x + a1.x; acc.y = a0.y + a1.y;
    acc.z = a0.z + a1.z; acc.w = a0.w + a1.w;

    float s = acc.x + acc.y + acc.z + acc.w;
#pragma unroll
    for (int o = 16; o; o >>= 1) s += __shfl_xor_sync(0xffffffffu, s, o);
    float mu = s * (1.0f / 128.0f);
    float d0 = acc.x - mu, d1 = acc.y - mu, d2 = acc.z - mu, d3 = acc.w - mu;
    float q = d0 * d0 + d1 * d1 + d2 * d2 + d3 * d3;
#pragma unroll
    for (int o = 16; o; o >>= 1) q += __shfl_xor_sync(0xffffffffu, q, o);
    float rs = rsqrtf(q * (1.0f / 128.0f) + 1e-5f);

    float4 gg = __ldg((const float4*)(g + lane * 4));
    float4 bb = __ldg((const float4*)(b + lane * 4));
    float4 o4;
    o4.x = fmaxf(fmaf(d0 * rs, gg.x, bb.x), 0.f);
    o4.y = fmaxf(fmaf(d1 * rs, gg.y, bb.y), 0.f);
    o4.z = fmaxf(fmaf(d2 * rs, gg.z, bb.z), 0.f);
    o4.w = fmaxf(fmaf(d3 * rs, gg.w, bb.w), 0.f);
    *(float4*)(g_h0 + (size_t)warp * IN_C + lane * 4) = o4;
}

// ---------------- edge scatter-add (mean numerator + counts) ---------------
// 8 edges per warp: 2x int4 index loads, 8 independent gather LDG.128s,
// 8 red.global.add.v4.f32 in flight (MLP 8 instead of 1).
__global__ void scatter_edges(const float* __restrict__ h, const int* __restrict__ src,
                              const int* __restrict__ dst, float* __restrict__ agg,
                              int* __restrict__ cnt, int E) {
    int warp = (blockIdx.x * blockDim.x + threadIdx.x) >> 5;
    int lane = threadIdx.x & 31;
    int e0 = warp * 8;
    if (e0 >= E) return;

    if (e0 + 8 <= E) {
        int4 sa = __ldg((const int4*)(src + e0));
        int4 sb = __ldg((const int4*)(src + e0 + 4));
        int4 da = __ldg((const int4*)(dst + e0));
        int4 db = __ldg((const int4*)(dst + e0 + 4));
        int s[8] = {sa.x, sa.y, sa.z, sa.w, sb.x, sb.y, sb.z, sb.w};
        int d[8] = {da.x, da.y, da.z, da.w, db.x, db.y, db.z, db.w};
        float4 v[8];
#pragma unroll
        for (int j = 0; j < 8; ++j)
            v[j] = __ldg((const float4*)(h + (size_t)s[j] * IN_C + lane * 4));
#pragma unroll
        for (int j = 0; j < 8; ++j) {
            float* p = agg + (size_t)d[j] * IN_C + lane * 4;
            asm volatile("red.global.add.v4.f32 [%0], {%1,%2,%3,%4};"
                         :: "l"(p), "f"(v[j].x), "f"(v[j].y), "f"(v[j].z), "f"(v[j].w)
                         : "memory");
        }
        if (lane < 8) {
            int dd = (lane == 0) ? da.x : (lane == 1) ? da.y : (lane == 2) ? da.z :
                     (lane == 3) ? da.w : (lane == 4) ? db.x : (lane == 5) ? db.y :
                     (lane == 6) ? db.z : db.w;
            asm volatile("red.global.add.u32 [%0], %1;" :: "l"(cnt + dd), "r"(1) : "memory");
        }
    } else {
        for (int e = e0; e < E; ++e) {
            int s = __ldg(src + e);
            int d = __ldg(dst + e);
            float4 v = __ldg((const float4*)(h + (size_t)s * IN_C + lane * 4));
            float* p = agg + (size_t)d * IN_C + lane * 4;
            asm volatile("red.global.add.v4.f32 [%0], {%1,%2,%3,%4};"
                         :: "l"(p), "f"(v.x), "f"(v.y), "f"(v.z), "f"(v.w)
                         : "memory");
            if (lane == 0)
                asm volatile("red.global.add.u32 [%0], %1;" :: "l"(cnt + d), "r"(1) : "memory");
        }
    }
}

// ---------------- fused SAGE GEMM: out = mean@Wl^T + bl + self@Wr^T (+relu)
// A = [mean | self] is [n, 256]; Wt is [256, 128] ([k][t]).
// Tile: 64 rows x 128 cols per block, 256 threads, 4x8 register blocking,
// packed f32x2 FMAs (16 FFMA2 per k-step per thread).
__global__ __launch_bounds__(256, 4)
void sage_gemm(const float* __restrict__ agg, const int* __restrict__ cnt,
               const float* __restrict__ selfh, const float* __restrict__ Wt,
               const float* __restrict__ bias, float* __restrict__ out,
               int n, int do_relu) {
    __shared__ float  As[64][33];
    __shared__ float4 Ws4[32][32];   // [kk][c/4]
    __shared__ float  rinv[64];
    __shared__ float  bs[128];

    int tid  = threadIdx.x;
    int row0 = blockIdx.x * 64;
    int tx = tid & 15;       // col group (8 cols)
    int ty = tid >> 4;       // row group (4 rows)

    if (tid < 64) {
        int r = row0 + tid;
        rinv[tid] = (r < n) ? (1.0f / fmaxf((float)__ldg(cnt + r), 1.0f)) : 0.0f;
    }
    if (tid < 128) bs[tid] = bias[tid];

    u64 accp[4][4];          // [row][col-pair], each holds 2 adjacent columns
#pragma unroll
    for (int r = 0; r < 4; ++r)
#pragma unroll
        for (int c = 0; c < 4; ++c) accp[r][c] = 0ull;

    for (int kb = 0; kb < 256; kb += 32) {
        __syncthreads();
        // load A tile: warp -> row slices, 32 consecutive k (coalesced)
        {
            int kk = tid & 31;
            int k  = kb + kk;
            for (int rr = tid >> 5; rr < 64; rr += 8) {
                int r = row0 + rr;
                float v = 0.f;
                if (r < n) {
                    if (k < 128) v = agg[(size_t)r * 128 + k] * rinv[rr];
                    else         v = selfh[(size_t)r * 128 + (k - 128)];
                }
                As[rr][kk] = v;
            }
        }
        // load W tile (float4, coalesced)
        for (int i = tid; i < 1024; i += 256) {
            int kk = i >> 5, c4 = i & 31;
            Ws4[kk][c4] = *(const float4*)(Wt + (size_t)(kb + kk) * 128 + c4 * 4);
        }
        __syncthreads();
#pragma unroll
        for (int kk = 0; kk < 32; ++kk) {
            u64 a0p = pack2(As[ty * 4 + 0][kk]);
            u64 a1p = pack2(As[ty * 4 + 1][kk]);
            u64 a2p = pack2(As[ty * 4 + 2][kk]);
            u64 a3p = pack2(As[ty * 4 + 3][kk]);
            ulonglong2 w0 = *(const ulonglong2*)&Ws4[kk][tx * 2 + 0];
            ulonglong2 w1 = *(const ulonglong2*)&Ws4[kk][tx * 2 + 1];
            u64 w[4] = {w0.x, w0.y, w1.x, w1.y};
#pragma unroll
            for (int c = 0; c < 4; ++c) {
                fma2(accp[0][c], a0p, w[c]);
                fma2(accp[1][c], a1p, w[c]);
                fma2(accp[2][c], a2p, w[c]);
                fma2(accp[3][c], a3p, w[c]);
            }
        }
    }

    // epilogue: unpack, bias (+relu), vectorized store
    int colb = tx * 8;
#pragma unroll
    for (int r = 0; r < 4; ++r) {
        int row = row0 + ty * 4 + r;
        if (row >= n) continue;
        float f[8];
#pragma unroll
        for (int c = 0; c < 4; ++c)
            unpack2(accp[r][c], f[2 * c], f[2 * c + 1]);
        float4 o0, o1;
        o0.x = f[0] + bs[colb + 0];
        o0.y = f[1] + bs[colb + 1];
        o0.z = f[2] + bs[colb + 2];
        o0.w = f[3] + bs[colb + 3];
        o1.x = f[4] + bs[colb + 4];
        o1.y = f[5] + bs[colb + 5];
        o1.z = f[6] + bs[colb + 6];
        o1.w = f[7] + bs[colb + 7];
        if (do_relu) {
            o0.x = fmaxf(o0.x, 0.f); o0.y = fmaxf(o0.y, 0.f);
            o0.z = fmaxf(o0.z, 0.f); o0.w = fmaxf(o0.w, 0.f);
            o1.x = fmaxf(o1.x, 0.f); o1.y = fmaxf(o1.y, 0.f);
            o1.z = fmaxf(o1.z, 0.f); o1.w = fmaxf(o1.w, 0.f);
        }
        *(float4*)(out + (size_t)row * 128 + colb)     = o0;
        *(float4*)(out + (size_t)row * 128 + colb + 4) = o1;
    }
}

// ---------------- host launcher --------------------------------------------
extern "C" void kernel_launch(void* const* d_in, const int* in_sizes, int n_in,
                              void* d_out, int out_size) {
    // input index layout: tolerate scalar inputs (n1, n2) present or absent
    int ix = 0, is1 = 1, id1 = 2, is2 = 3, id2 = 4;
    int iemb, ig, ib, iwl1, ibl1, iwr1, iwl2, ibl2, iwr2;
    if (n_in >= 16) {
        iemb = 7; ig = 8; ib = 9; iwl1 = 10; ibl1 = 11; iwr1 = 12;
        iwl2 = 13; ibl2 = 14; iwr2 = 15;
    } else {
        iemb = 5; ig = 6; ib = 7; iwl1 = 8; ibl1 = 9; iwr1 = 10;
        iwl2 = 11; ibl2 = 12; iwr2 = 13;
    }

    const int*   x    = (const int*)d_in[ix];
    const int*   src1 = (const int*)d_in[is1];
    const int*   dst1 = (const int*)d_in[id1];
    const int*   src2 = (const int*)d_in[is2];
    const int*   dst2 = (const int*)d_in[id2];
    const float* emb  = (const float*)d_in[iemb];
    const float* ln_g = (const float*)d_in[ig];
    const float* ln_b = (const float*)d_in[ib];
    const float* Wl1  = (const float*)d_in[iwl1];
    const float* bl1  = (const float*)d_in[ibl1];
    const float* Wr1  = (const float*)d_in[iwr1];
    const float* Wl2  = (const float*)d_in[iwl2];
    const float* bl2  = (const float*)d_in[ibl2];
    const float* Wr2  = (const float*)d_in[iwr2];

    int N0 = in_sizes[ix] / W_BAG;
    int E1 = in_sizes[is1];
    int E2 = in_sizes[is2];

    float *h0, *h1, *agg1, *agg2, *wt1, *wt2;
    int *cnt1, *cnt2;
    cudaGetSymbolAddress((void**)&h0,   g_h0);
    cudaGetSymbolAddress((void**)&h1,   g_h1);
    cudaGetSymbolAddress((void**)&agg1, g_agg1);
    cudaGetSymbolAddress((void**)&agg2, g_agg2);
    cudaGetSymbolAddress((void**)&cnt1, g_cnt1);
    cudaGetSymbolAddress((void**)&cnt2, g_cnt2);
    cudaGetSymbolAddress((void**)&wt1,  g_Wt1);
    cudaGetSymbolAddress((void**)&wt2,  g_Wt2);

    // 1. zero accumulators + weight transpose (single launch)
    init_scratch<<<512, 256>>>(Wl1, Wr1, Wl2, Wr2);

    // 2. embedding bag + LN + relu -> h0  (one warp per row)
    embed_ln_relu<<<(N0 * 32 + 255) / 256, 256>>>(x, emb, ln_g, ln_b, N0);

    // 3. layer-1 aggregation (8 edges/warp)
    scatter_edges<<<(E1 + 63) / 64, 256>>>(h0, src1, dst1, agg1, cnt1, E1);

    // 4. layer-1 fused GEMM + relu -> h1
    sage_gemm<<<(N1_C + 63) / 64, 256>>>(agg1, cnt1, h0, wt1, bl1, h1, N1_C, 1);

    // 5. layer-2 aggregation
    scatter_edges<<<(E2 + 63) / 64, 256>>>(h1, src2, dst2, agg2, cnt2, E2);

    // 6. layer-2 fused GEMM -> d_out
    sage_gemm<<<(N2_C + 63) / 64, 256>>>(agg2, cnt2, h1, wt2, bl2, (float*)d_out,
                                         N2_C, 0);
}

// round 5
// speedup vs baseline: 1.1017x; 1.0040x over previous
#include <cuda_runtime.h>
#include <cstdint>

// ---------------- problem constants (fixed by the dataset) ----------------
#define IN_C   128
#define LEAF   50000
#define N0_MAX 100000
#define W_BAG  16
#define N1_C   25000
#define N2_C   5000

typedef unsigned long long u64;

// ---------------- device scratch (allocation-free rule) -------------------
__device__ float g_h0[(size_t)N0_MAX * IN_C];     // 51.2 MB  embed+LN+relu
__device__ float g_h1[(size_t)N1_C * IN_C];       // 12.8 MB  sage1 output (relu'd)
__device__ float g_agg1[(size_t)N1_C * IN_C];     // 12.8 MB
__device__ float g_agg2[(size_t)N2_C * IN_C];     //  2.6 MB
__device__ int   g_cnt1[N1_C];
__device__ int   g_cnt2[N2_C];
__device__ float g_Wt1[256 * 128];                // [k][t] combined (Wl|Wr) transposed
__device__ float g_Wt2[256 * 128];

// ---------------- f32x2 packed-FMA helpers ---------------------------------
__device__ __forceinline__ u64 pack2(float a) {
    u64 r;
    unsigned ai = __float_as_uint(a);
    asm("mov.b64 %0, {%1, %1};" : "=l"(r) : "r"(ai));
    return r;
}
__device__ __forceinline__ void fma2(u64& d, u64 a, u64 b) {
    asm("fma.rn.f32x2 %0, %1, %2, %0;" : "+l"(d) : "l"(a), "l"(b));
}
__device__ __forceinline__ void unpack2(u64 v, float& lo, float& hi) {
    unsigned l, h;
    asm("mov.b64 {%0, %1}, %2;" : "=r"(l), "=r"(h) : "l"(v));
    lo = __uint_as_float(l);
    hi = __uint_as_float(h);
}

// ---------------- zero accumulators + weight transpose (one launch) --------
__global__ void init_scratch(const float* __restrict__ Wl1, const float* __restrict__ Wr1,
                             const float* __restrict__ Wl2, const float* __restrict__ Wr2) {
    int i  = blockIdx.x * blockDim.x + threadIdx.x;
    int st = gridDim.x * blockDim.x;
    for (int j = i; j < N1_C * IN_C; j += st) g_agg1[j] = 0.f;
    for (int j = i; j < N2_C * IN_C; j += st) g_agg2[j] = 0.f;
    for (int j = i; j < N1_C; j += st) g_cnt1[j] = 0;
    for (int j = i; j < N2_C; j += st) g_cnt2[j] = 0;
    for (int j = i; j < 256 * 128; j += st) {
        int k = j >> 7;
        int t = j & 127;
        g_Wt1[j] = (k < 128) ? Wl1[t * 128 + k] : Wr1[t * 128 + (k - 128)];
        g_Wt2[j] = (k < 128) ? Wl2[t * 128 + k] : Wr2[t * 128 + (k - 128)];
    }
}

// ---------------- embedding bag sum + layernorm + relu ---------------------
// one warp per row; bag indices loaded once (lane-distributed) and broadcast
// via shfl; all 16 gather loads independent -> MLP 16.
__global__ void embed_ln_relu(const int* __restrict__ x, const float* __restrict__ emb,
                              const float* __restrict__ g, const float* __restrict__ b,
                              int N0) {
    int warp = (blockIdx.x * blockDim.x + threadIdx.x) >> 5;
    int lane = threadIdx.x & 31;
    if (warp >= N0) return;

    int idx_l = (lane < W_BAG) ? __ldg(x + (size_t)warp * W_BAG + lane) : 0;

    float4 a0 = make_float4(0.f, 0.f, 0.f, 0.f);
    float4 a1 = make_float4(0.f, 0.f, 0.f, 0.f);
#pragma unroll
    for (int w = 0; w < W_BAG; w += 2) {
        int i0 = __shfl_sync(0xffffffffu, idx_l, w);
        int i1 = __shfl_sync(0xffffffffu, idx_l, w + 1);
        float4 e0 = __ldg((const float4*)(emb + (size_t)i0 * IN_C + lane * 4));
        float4 e1 = __ldg((const float4*)(emb + (size_t)i1 * IN_C + lane * 4));
        a0.x += e0.x; a0.y += e0.y; a0.z += e0.z; a0.w += e0.w;
        a1.x += e1.x; a1.y += e1.y; a1.z += e1.z; a1.w += e1.w;
    }
    float4 acc;
    acc.x = a0.x + a1.x; acc.y = a0.y + a1.y;
    acc.z = a0.z + a1.z; acc.w = a0.w + a1.w;

    float s = acc.x + acc.y + acc.z + acc.w;
#pragma unroll
    for (int o = 16; o; o >>= 1) s += __shfl_xor_sync(0xffffffffu, s, o);
    float mu = s * (1.0f / 128.0f);
    float d0 = acc.x - mu, d1 = acc.y - mu, d2 = acc.z - mu, d3 = acc.w - mu;
    float q = d0 * d0 + d1 * d1 + d2 * d2 + d3 * d3;
#pragma unroll
    for (int o = 16; o; o >>= 1) q += __shfl_xor_sync(0xffffffffu, q, o);
    float rs = rsqrtf(q * (1.0f / 128.0f) + 1e-5f);

    float4 gg = __ldg((const float4*)(g + lane * 4));
    float4 bb = __ldg((const float4*)(b + lane * 4));
    float4 o4;
    o4.x = fmaxf(fmaf(d0 * rs, gg.x, bb.x), 0.f);
    o4.y = fmaxf(fmaf(d1 * rs, gg.y, bb.y), 0.f);
    o4.z = fmaxf(fmaf(d2 * rs, gg.z, bb.z), 0.f);
    o4.w = fmaxf(fmaf(d3 * rs, gg.w, bb.w), 0.f);
    *(float4*)(g_h0 + (size_t)warp * IN_C + lane * 4) = o4;
}

// ---------------- edge scatter-add (mean numerator + counts) ---------------
// 8 edges per warp: 2x int4 index loads, 8 independent gather LDG.128s,
// 8 red.global.add.v4.f32 in flight (MLP 8 instead of 1).
__global__ void scatter_edges(const float* __restrict__ h, const int* __restrict__ src,
                              const int* __restrict__ dst, float* __restrict__ agg,
                              int* __restrict__ cnt, int E) {
    int warp = (blockIdx.x * blockDim.x + threadIdx.x) >> 5;
    int lane = threadIdx.x & 31;
    int e0 = warp * 8;
    if (e0 >= E) return;

    if (e0 + 8 <= E) {
        int4 sa = __ldg((const int4*)(src + e0));
        int4 sb = __ldg((const int4*)(src + e0 + 4));
        int4 da = __ldg((const int4*)(dst + e0));
        int4 db = __ldg((const int4*)(dst + e0 + 4));
        int s[8] = {sa.x, sa.y, sa.z, sa.w, sb.x, sb.y, sb.z, sb.w};
        int d[8] = {da.x, da.y, da.z, da.w, db.x, db.y, db.z, db.w};
        float4 v[8];
#pragma unroll
        for (int j = 0; j < 8; ++j)
            v[j] = __ldg((const float4*)(h + (size_t)s[j] * IN_C + lane * 4));
#pragma unroll
        for (int j = 0; j < 8; ++j) {
            float* p = agg + (size_t)d[j] * IN_C + lane * 4;
            asm volatile("red.global.add.v4.f32 [%0], {%1,%2,%3,%4};"
                         :: "l"(p), "f"(v[j].x), "f"(v[j].y), "f"(v[j].z), "f"(v[j].w)
                         : "memory");
        }
        if (lane < 8) {
            int dd = (lane == 0) ? da.x : (lane == 1) ? da.y : (lane == 2) ? da.z :
                     (lane == 3) ? da.w : (lane == 4) ? db.x : (lane == 5) ? db.y :
                     (lane == 6) ? db.z : db.w;
            asm volatile("red.global.add.u32 [%0], %1;" :: "l"(cnt + dd), "r"(1) : "memory");
        }
    } else {
        for (int e = e0; e < E; ++e) {
            int s = __ldg(src + e);
            int d = __ldg(dst + e);
            float4 v = __ldg((const float4*)(h + (size_t)s * IN_C + lane * 4));
            float* p = agg + (size_t)d * IN_C + lane * 4;
            asm volatile("red.global.add.v4.f32 [%0], {%1,%2,%3,%4};"
                         :: "l"(p), "f"(v.x), "f"(v.y), "f"(v.z), "f"(v.w)
                         : "memory");
            if (lane == 0)
                asm volatile("red.global.add.u32 [%0], %1;" :: "l"(cnt + d), "r"(1) : "memory");
        }
    }
}

// ---------------- fused SAGE GEMM: out = mean@Wl^T + bl + self@Wr^T (+relu)
// A = [mean | self] is [n, 256]; Wt is [256, 128] ([k][t]).
// Tile: 64 rows x 128 cols per block, 256 threads, 4x8 register blocking,
// packed f32x2 FMAs (16 FFMA2 per k-step per thread).
__global__ __launch_bounds__(256, 4)
void sage_gemm(const float* __restrict__ agg, const int* __restrict__ cnt,
               const float* __restrict__ selfh, const float* __restrict__ Wt,
               const float* __restrict__ bias, float* __restrict__ out,
               int n, int do_relu) {
    __shared__ float  As[64][33];
    __shared__ float4 Ws4[32][32];   // [kk][c/4]
    __shared__ float  rinv[64];
    __shared__ float  bs[128];

    int tid  = threadIdx.x;
    int row0 = blockIdx.x * 64;
    int tx = tid & 15;       // col group (8 cols)
    int ty = tid >> 4;       // row group (4 rows)

    if (tid < 64) {
        int r = row0 + tid;
        rinv[tid] = (r < n) ? (1.0f / fmaxf((float)__ldg(cnt + r), 1.0f)) : 0.0f;
    }
    if (tid < 128) bs[tid] = bias[tid];

    u64 accp[4][4];          // [row][col-pair], each holds 2 adjacent columns
#pragma unroll
    for (int r = 0; r < 4; ++r)
#pragma unroll
        for (int c = 0; c < 4; ++c) accp[r][c] = 0ull;

    for (int kb = 0; kb < 256; kb += 32) {
        __syncthreads();
        // load A tile: warp -> row slices, 32 consecutive k (coalesced)
        {
            int kk = tid & 31;
            int k  = kb + kk;
            for (int rr = tid >> 5; rr < 64; rr += 8) {
                int r = row0 + rr;
                float v = 0.f;
                if (r < n) {
                    if (k < 128) v = agg[(size_t)r * 128 + k] * rinv[rr];
                    else         v = selfh[(size_t)r * 128 + (k - 128)];
                }
                As[rr][kk] = v;
            }
        }
        // load W tile (float4, coalesced)
        for (int i = tid; i < 1024; i += 256) {
            int kk = i >> 5, c4 = i & 31;
            Ws4[kk][c4] = *(const float4*)(Wt + (size_t)(kb + kk) * 128 + c4 * 4);
        }
        __syncthreads();
#pragma unroll
        for (int kk = 0; kk < 32; ++kk) {
            u64 a0p = pack2(As[ty * 4 + 0][kk]);
            u64 a1p = pack2(As[ty * 4 + 1][kk]);
            u64 a2p = pack2(As[ty * 4 + 2][kk]);
            u64 a3p = pack2(As[ty * 4 + 3][kk]);
            ulonglong2 w0 = *(const ulonglong2*)&Ws4[kk][tx * 2 + 0];
            ulonglong2 w1 = *(const ulonglong2*)&Ws4[kk][tx * 2 + 1];
            u64 w[4] = {w0.x, w0.y, w1.x, w1.y};
#pragma unroll
            for (int c = 0; c < 4; ++c) {
                fma2(accp[0][c], a0p, w[c]);
                fma2(accp[1][c], a1p, w[c]);
                fma2(accp[2][c], a2p, w[c]);
                fma2(accp[3][c], a3p, w[c]);
            }
        }
    }

    // epilogue: unpack, bias (+relu), vectorized store
    int colb = tx * 8;
#pragma unroll
    for (int r = 0; r < 4; ++r) {
        int row = row0 + ty * 4 + r;
        if (row >= n) continue;
        float f[8];
#pragma unroll
        for (int c = 0; c < 4; ++c)
            unpack2(accp[r][c], f[2 * c], f[2 * c + 1]);
        float4 o0, o1;
        o0.x = f[0] + bs[colb + 0];
        o0.y = f[1] + bs[colb + 1];
        o0.z = f[2] + bs[colb + 2];
        o0.w = f[3] + bs[colb + 3];
        o1.x = f[4] + bs[colb + 4];
        o1.y = f[5] + bs[colb + 5];
        o1.z = f[6] + bs[colb + 6];
        o1.w = f[7] + bs[colb + 7];
        if (do_relu) {
            o0.x = fmaxf(o0.x, 0.f); o0.y = fmaxf(o0.y, 0.f);
            o0.z = fmaxf(o0.z, 0.f); o0.w = fmaxf(o0.w, 0.f);
            o1.x = fmaxf(o1.x, 0.f); o1.y = fmaxf(o1.y, 0.f);
            o1.z = fmaxf(o1.z, 0.f); o1.w = fmaxf(o1.w, 0.f);
        }
        *(float4*)(out + (size_t)row * 128 + colb)     = o0;
        *(float4*)(out + (size_t)row * 128 + colb + 4) = o1;
    }
}

// ---------------- host launcher --------------------------------------------
extern "C" void kernel_launch(void* const* d_in, const int* in_sizes, int n_in,
                              void* d_out, int out_size) {
    // input index layout: tolerate scalar inputs (n1, n2) present or absent
    int ix = 0, is1 = 1, id1 = 2, is2 = 3, id2 = 4;
    int iemb, ig, ib, iwl1, ibl1, iwr1, iwl2, ibl2, iwr2;
    if (n_in >= 16) {
        iemb = 7; ig = 8; ib = 9; iwl1 = 10; ibl1 = 11; iwr1 = 12;
        iwl2 = 13; ibl2 = 14; iwr2 = 15;
    } else {
        iemb = 5; ig = 6; ib = 7; iwl1 = 8; ibl1 = 9; iwr1 = 10;
        iwl2 = 11; ibl2 = 12; iwr2 = 13;
    }

    const int*   x    = (const int*)d_in[ix];
    const int*   src1 = (const int*)d_in[is1];
    const int*   dst1 = (const int*)d_in[id1];
    const int*   src2 = (const int*)d_in[is2];
    const int*   dst2 = (const int*)d_in[id2];
    const float* emb  = (const float*)d_in[iemb];
    const float* ln_g = (const float*)d_in[ig];
    const float* ln_b = (const float*)d_in[ib];
    const float* Wl1  = (const float*)d_in[iwl1];
    const float* bl1  = (const float*)d_in[ibl1];
    const float* Wr1  = (const float*)d_in[iwr1];
    const float* Wl2  = (const float*)d_in[iwl2];
    const float* bl2  = (const float*)d_in[ibl2];
    const float* Wr2  = (const float*)d_in[iwr2];

    int N0 = in_sizes[ix] / W_BAG;
    int E1 = in_sizes[is1];
    int E2 = in_sizes[is2];

    float *h0, *h1, *agg1, *agg2, *wt1, *wt2;
    int *cnt1, *cnt2;
    cudaGetSymbolAddress((void**)&h0,   g_h0);
    cudaGetSymbolAddress((void**)&h1,   g_h1);
    cudaGetSymbolAddress((void**)&agg1, g_agg1);
    cudaGetSymbolAddress((void**)&agg2, g_agg2);
    cudaGetSymbolAddress((void**)&cnt1, g_cnt1);
    cudaGetSymbolAddress((void**)&cnt2, g_cnt2);
    cudaGetSymbolAddress((void**)&wt1,  g_Wt1);
    cudaGetSymbolAddress((void**)&wt2,  g_Wt2);

    // 1. zero accumulators + weight transpose (single launch)
    init_scratch<<<512, 256>>>(Wl1, Wr1, Wl2, Wr2);

    // 2. embedding bag + LN + relu -> h0  (one warp per row)
    embed_ln_relu<<<(N0 * 32 + 255) / 256, 256>>>(x, emb, ln_g, ln_b, N0);

    // 3. layer-1 aggregation (8 edges/warp)
    scatter_edges<<<(E1 + 63) / 64, 256>>>(h0, src1, dst1, agg1, cnt1, E1);

    // 4. layer-1 fused GEMM + relu -> h1
    sage_gemm<<<(N1_C + 63) / 64, 256>>>(agg1, cnt1, h0, wt1, bl1, h1, N1_C, 1);

    // 5. layer-2 aggregation
    scatter_edges<<<(E2 + 63) / 64, 256>>>(h1, src2, dst2, agg2, cnt2, E2);

    // 6. layer-2 fused GEMM -> d_out
    sage_gemm<<<(N2_C + 63) / 64, 256>>>(agg2, cnt2, h1, wt2, bl2, (float*)d_out,
                                         N2_C, 0);
}

// round 6
// speedup vs baseline: 1.1916x; 1.0816x over previous
#include <cuda_runtime.h>
#include <cstdint>

// ---------------- problem constants (fixed by the dataset) ----------------
#define IN_C   128
#define LEAF   50000
#define N0_MAX 100000
#define W_BAG  16
#define N1_C   25000
#define N2_C   5000

typedef unsigned long long u64;

// ---------------- device scratch (allocation-free rule) -------------------
__device__ float g_h0[(size_t)N0_MAX * IN_C];     // 51.2 MB  embed+LN+relu
__device__ float g_h1[(size_t)N1_C * IN_C];       // 12.8 MB  sage1 output (relu'd)
__device__ float g_agg1[(size_t)N1_C * IN_C];     // 12.8 MB
__device__ float g_agg2[(size_t)N2_C * IN_C];     //  2.6 MB
__device__ int   g_cnt1[N1_C];
__device__ int   g_cnt2[N2_C];
__device__ float g_Wt1[256 * 128];                // [k][t] combined (Wl|Wr) transposed
__device__ float g_Wt2[256 * 128];

// ---------------- f32x2 packed-FMA helpers ---------------------------------
__device__ __forceinline__ u64 pack2(float a) {
    u64 r;
    unsigned ai = __float_as_uint(a);
    asm("mov.b64 %0, {%1, %1};" : "=l"(r) : "r"(ai));
    return r;
}
__device__ __forceinline__ void fma2(u64& d, u64 a, u64 b) {
    asm("fma.rn.f32x2 %0, %1, %2, %0;" : "+l"(d) : "l"(a), "l"(b));
}
__device__ __forceinline__ void unpack2(u64 v, float& lo, float& hi) {
    unsigned l, h;
    asm("mov.b64 {%0, %1}, %2;" : "=r"(l), "=r"(h) : "l"(v));
    lo = __uint_as_float(l);
    hi = __uint_as_float(h);
}

// ---------------- zero accumulators + weight transpose (one launch) --------
__global__ void init_scratch(const float* __restrict__ Wl1, const float* __restrict__ Wr1,
                             const float* __restrict__ Wl2, const float* __restrict__ Wr2) {
    int i  = blockIdx.x * blockDim.x + threadIdx.x;
    int st = gridDim.x * blockDim.x;
    for (int j = i; j < N1_C * IN_C; j += st) g_agg1[j] = 0.f;
    for (int j = i; j < N2_C * IN_C; j += st) g_agg2[j] = 0.f;
    for (int j = i; j < N1_C; j += st) g_cnt1[j] = 0;
    for (int j = i; j < N2_C; j += st) g_cnt2[j] = 0;
    for (int j = i; j < 256 * 128; j += st) {
        int k = j >> 7;
        int t = j & 127;
        g_Wt1[j] = (k < 128) ? Wl1[t * 128 + k] : Wr1[t * 128 + (k - 128)];
        g_Wt2[j] = (k < 128) ? Wl2[t * 128 + k] : Wr2[t * 128 + (k - 128)];
    }
}

// ---------------- embedding bag sum + layernorm + relu ---------------------
__global__ void embed_ln_relu(const int* __restrict__ x, const float* __restrict__ emb,
                              const float* __restrict__ g, const float* __restrict__ b,
                              int N0) {
    int warp = (blockIdx.x * blockDim.x + threadIdx.x) >> 5;
    int lane = threadIdx.x & 31;
    if (warp >= N0) return;

    int idx_l = (lane < W_BAG) ? __ldg(x + (size_t)warp * W_BAG + lane) : 0;

    float4 a0 = make_float4(0.f, 0.f, 0.f, 0.f);
    float4 a1 = make_float4(0.f, 0.f, 0.f, 0.f);
#pragma unroll
    for (int w = 0; w < W_BAG; w += 2) {
        int i0 = __shfl_sync(0xffffffffu, idx_l, w);
        int i1 = __shfl_sync(0xffffffffu, idx_l, w + 1);
        float4 e0 = __ldg((const float4*)(emb + (size_t)i0 * IN_C + lane * 4));
        float4 e1 = __ldg((const float4*)(emb + (size_t)i1 * IN_C + lane * 4));
        a0.x += e0.x; a0.y += e0.y; a0.z += e0.z; a0.w += e0.w;
        a1.x += e1.x; a1.y += e1.y; a1.z += e1.z; a1.w += e1.w;
    }
    float4 acc;
    acc.x = a0.x + a1.x; acc.y = a0.y + a1.y;
    acc.z = a0.z + a1.z; acc.w = a0.w + a1.w;

    float s = acc.x + acc.y + acc.z + acc.w;
#pragma unroll
    for (int o = 16; o; o >>= 1) s += __shfl_xor_sync(0xffffffffu, s, o);
    float mu = s * (1.0f / 128.0f);
    float d0 = acc.x - mu, d1 = acc.y - mu, d2 = acc.z - mu, d3 = acc.w - mu;
    float q = d0 * d0 + d1 * d1 + d2 * d2 + d3 * d3;
#pragma unroll
    for (int o = 16; o; o >>= 1) q += __shfl_xor_sync(0xffffffffu, q, o);
    float rs = rsqrtf(q * (1.0f / 128.0f) + 1e-5f);

    float4 gg = __ldg((const float4*)(g + lane * 4));
    float4 bb = __ldg((const float4*)(b + lane * 4));
    float4 o4;
    o4.x = fmaxf(fmaf(d0 * rs, gg.x, bb.x), 0.f);
    o4.y = fmaxf(fmaf(d1 * rs, gg.y, bb.y), 0.f);
    o4.z = fmaxf(fmaf(d2 * rs, gg.z, bb.z), 0.f);
    o4.w = fmaxf(fmaf(d3 * rs, gg.w, bb.w), 0.f);
    *(float4*)(g_h0 + (size_t)warp * IN_C + lane * 4) = o4;
}

// ---------------- edge scatter-add (mean numerator + counts) ---------------
__global__ void scatter_edges(const float* __restrict__ h, const int* __restrict__ src,
                              const int* __restrict__ dst, float* __restrict__ agg,
                              int* __restrict__ cnt, int E) {
    int warp = (blockIdx.x * blockDim.x + threadIdx.x) >> 5;
    int lane = threadIdx.x & 31;
    int e0 = warp * 8;
    if (e0 >= E) return;

    if (e0 + 8 <= E) {
        int4 sa = __ldg((const int4*)(src + e0));
        int4 sb = __ldg((const int4*)(src + e0 + 4));
        int4 da = __ldg((const int4*)(dst + e0));
        int4 db = __ldg((const int4*)(dst + e0 + 4));
        int s[8] = {sa.x, sa.y, sa.z, sa.w, sb.x, sb.y, sb.z, sb.w};
        int d[8] = {da.x, da.y, da.z, da.w, db.x, db.y, db.z, db.w};
        float4 v[8];
#pragma unroll
        for (int j = 0; j < 8; ++j)
            v[j] = __ldg((const float4*)(h + (size_t)s[j] * IN_C + lane * 4));
#pragma unroll
        for (int j = 0; j < 8; ++j) {
            float* p = agg + (size_t)d[j] * IN_C + lane * 4;
            asm volatile("red.global.add.v4.f32 [%0], {%1,%2,%3,%4};"
                         :: "l"(p), "f"(v[j].x), "f"(v[j].y), "f"(v[j].z), "f"(v[j].w)
                         : "memory");
        }
        if (lane < 8) {
            int dd = (lane == 0) ? da.x : (lane == 1) ? da.y : (lane == 2) ? da.z :
                     (lane == 3) ? da.w : (lane == 4) ? db.x : (lane == 5) ? db.y :
                     (lane == 6) ? db.z : db.w;
            asm volatile("red.global.add.u32 [%0], %1;" :: "l"(cnt + dd), "r"(1) : "memory");
        }
    } else {
        for (int e = e0; e < E; ++e) {
            int s = __ldg(src + e);
            int d = __ldg(dst + e);
            float4 v = __ldg((const float4*)(h + (size_t)s * IN_C + lane * 4));
            float* p = agg + (size_t)d * IN_C + lane * 4;
            asm volatile("red.global.add.v4.f32 [%0], {%1,%2,%3,%4};"
                         :: "l"(p), "f"(v.x), "f"(v.y), "f"(v.z), "f"(v.w)
                         : "memory");
            if (lane == 0)
                asm volatile("red.global.add.u32 [%0], %1;" :: "l"(cnt + d), "r"(1) : "memory");
        }
    }
}

// ---------------- fused SAGE GEMM: out = mean@Wl^T + bl + self@Wr^T (+relu)
// A = [mean | self] is [n, 256]; Wt is [256, 128] ([k][t]).
// Register-staged double-buffered pipeline: 1 barrier per 32-k chunk,
// global loads for chunk c+1 overlap compute on chunk c.
// TM=64 -> thread tile 4x8; TM=32 -> thread tile 2x8. Packed f32x2 FMAs.
template<int TM, int DO_RELU>
__global__ __launch_bounds__(256)
void sage_gemm(const float* __restrict__ agg, const int* __restrict__ cnt,
               const float* __restrict__ selfh, const float* __restrict__ Wt,
               const float* __restrict__ bias, float* __restrict__ out, int n) {
    constexpr int RPT = TM / 16;   // output rows per thread
    constexpr int ALD = TM / 8;    // A elements per thread per chunk

    __shared__ float  As[2][TM][34];     // pad 34 keeps float2(kk) 8B-aligned
    __shared__ float4 Ws4[2][32][32];    // [kk][c/4]
    __shared__ float  rinv[TM];
    __shared__ float  bs[128];

    int tid  = threadIdx.x;
    int row0 = blockIdx.x * TM;
    int tx = tid & 15;       // col group (8 cols)
    int ty = tid >> 4;       // row group (RPT rows)

    if (tid < TM) {
        int r = row0 + tid;
        rinv[tid] = (r < n) ? (1.0f / fmaxf((float)__ldg(cnt + r), 1.0f)) : 0.0f;
    }
    if (tid >= 128) bs[tid - 128] = bias[tid - 128];
    __syncthreads();   // rinv visible to all A-tile loaders

    int kk    = tid & 31;
    int rbase = tid >> 5;

    float  a_reg[ALD];
    float4 w_reg[4];

    auto load_chunk = [&](int c) {
#pragma unroll
        for (int i = 0; i < ALD; ++i) {
            int rr = rbase + i * 8;
            int r  = row0 + rr;
            float v = 0.f;
            if (r < n) {
                if (c < 4) v = agg[(size_t)r * 128 + c * 32 + kk] * rinv[rr];
                else       v = selfh[(size_t)r * 128 + (c - 4) * 32 + kk];
            }
            a_reg[i] = v;
        }
#pragma unroll
        for (int i = 0; i < 4; ++i) {
            int idx = tid + i * 256;
            int wk = idx >> 5, c4 = idx & 31;
            w_reg[i] = *(const float4*)(Wt + (size_t)(c * 32 + wk) * 128 + c4 * 4);
        }
    };
    auto store_chunk = [&](int buf) {
#pragma unroll
        for (int i = 0; i < ALD; ++i)
            As[buf][rbase + i * 8][kk] = a_reg[i];
#pragma unroll
        for (int i = 0; i < 4; ++i) {
            int idx = tid + i * 256;
            Ws4[buf][idx >> 5][idx & 31] = w_reg[i];
        }
    };

    u64 accp[RPT][4];
#pragma unroll
    for (int r = 0; r < RPT; ++r)
#pragma unroll
        for (int c = 0; c < 4; ++c) accp[r][c] = 0ull;

    load_chunk(0);
    store_chunk(0);
    __syncthreads();

#pragma unroll
    for (int c = 0; c < 8; ++c) {
        if (c < 7) load_chunk(c + 1);      // global -> regs, overlaps compute
        int buf = c & 1;
#pragma unroll
        for (int k2 = 0; k2 < 32; k2 += 2) {
            u64 ap0[RPT], ap1[RPT];
#pragma unroll
            for (int r = 0; r < RPT; ++r) {
                float2 a2 = *(const float2*)&As[buf][ty * RPT + r][k2];
                ap0[r] = pack2(a2.x);
                ap1[r] = pack2(a2.y);
            }
            ulonglong2 w00 = *(const ulonglong2*)&Ws4[buf][k2][tx * 2 + 0];
            ulonglong2 w01 = *(const ulonglong2*)&Ws4[buf][k2][tx * 2 + 1];
            ulonglong2 w10 = *(const ulonglong2*)&Ws4[buf][k2 + 1][tx * 2 + 0];
            ulonglong2 w11 = *(const ulonglong2*)&Ws4[buf][k2 + 1][tx * 2 + 1];
            u64 wa[4] = {w00.x, w00.y, w01.x, w01.y};
            u64 wb[4] = {w10.x, w10.y, w11.x, w11.y};
#pragma unroll
            for (int r = 0; r < RPT; ++r) {
#pragma unroll
                for (int cc = 0; cc < 4; ++cc) {
                    fma2(accp[r][cc], ap0[r], wa[cc]);
                    fma2(accp[r][cc], ap1[r], wb[cc]);
                }
            }
        }
        if (c < 7) store_chunk((c + 1) & 1);  // other buffer; prev reads done
        __syncthreads();
    }

    // epilogue: unpack, bias (+relu), vectorized store
    int colb = tx * 8;
#pragma unroll
    for (int r = 0; r < RPT; ++r) {
        int row = row0 + ty * RPT + r;
        if (row >= n) continue;
        float f[8];
#pragma unroll
        for (int c = 0; c < 4; ++c)
            unpack2(accp[r][c], f[2 * c], f[2 * c + 1]);
        float4 o0, o1;
        o0.x = f[0] + bs[colb + 0];
        o0.y = f[1] + bs[colb + 1];
        o0.z = f[2] + bs[colb + 2];
        o0.w = f[3] + bs[colb + 3];
        o1.x = f[4] + bs[colb + 4];
        o1.y = f[5] + bs[colb + 5];
        o1.z = f[6] + bs[colb + 6];
        o1.w = f[7] + bs[colb + 7];
        if (DO_RELU) {
            o0.x = fmaxf(o0.x, 0.f); o0.y = fmaxf(o0.y, 0.f);
            o0.z = fmaxf(o0.z, 0.f); o0.w = fmaxf(o0.w, 0.f);
            o1.x = fmaxf(o1.x, 0.f); o1.y = fmaxf(o1.y, 0.f);
            o1.z = fmaxf(o1.z, 0.f); o1.w = fmaxf(o1.w, 0.f);
        }
        *(float4*)(out + (size_t)row * 128 + colb)     = o0;
        *(float4*)(out + (size_t)row * 128 + colb + 4) = o1;
    }
}

// ---------------- host launcher --------------------------------------------
extern "C" void kernel_launch(void* const* d_in, const int* in_sizes, int n_in,
                              void* d_out, int out_size) {
    int ix = 0, is1 = 1, id1 = 2, is2 = 3, id2 = 4;
    int iemb, ig, ib, iwl1, ibl1, iwr1, iwl2, ibl2, iwr2;
    if (n_in >= 16) {
        iemb = 7; ig = 8; ib = 9; iwl1 = 10; ibl1 = 11; iwr1 = 12;
        iwl2 = 13; ibl2 = 14; iwr2 = 15;
    } else {
        iemb = 5; ig = 6; ib = 7; iwl1 = 8; ibl1 = 9; iwr1 = 10;
        iwl2 = 11; ibl2 = 12; iwr2 = 13;
    }

    const int*   x    = (const int*)d_in[ix];
    const int*   src1 = (const int*)d_in[is1];
    const int*   dst1 = (const int*)d_in[id1];
    const int*   src2 = (const int*)d_in[is2];
    const int*   dst2 = (const int*)d_in[id2];
    const float* emb  = (const float*)d_in[iemb];
    const float* ln_g = (const float*)d_in[ig];
    const float* ln_b = (const float*)d_in[ib];
    const float* Wl1  = (const float*)d_in[iwl1];
    const float* bl1  = (const float*)d_in[ibl1];
    const float* Wr1  = (const float*)d_in[iwr1];
    const float* Wl2  = (const float*)d_in[iwl2];
    const float* bl2  = (const float*)d_in[ibl2];
    const float* Wr2  = (const float*)d_in[iwr2];

    int N0 = in_sizes[ix] / W_BAG;
    int E1 = in_sizes[is1];
    int E2 = in_sizes[is2];

    float *h0, *h1, *agg1, *agg2, *wt1, *wt2;
    int *cnt1, *cnt2;
    cudaGetSymbolAddress((void**)&h0,   g_h0);
    cudaGetSymbolAddress((void**)&h1,   g_h1);
    cudaGetSymbolAddress((void**)&agg1, g_agg1);
    cudaGetSymbolAddress((void**)&agg2, g_agg2);
    cudaGetSymbolAddress((void**)&cnt1, g_cnt1);
    cudaGetSymbolAddress((void**)&cnt2, g_cnt2);
    cudaGetSymbolAddress((void**)&wt1,  g_Wt1);
    cudaGetSymbolAddress((void**)&wt2,  g_Wt2);

    // 1. zero accumulators + weight transpose (single launch)
    init_scratch<<<512, 256>>>(Wl1, Wr1, Wl2, Wr2);

    // 2. embedding bag + LN + relu -> h0  (one warp per row)
    embed_ln_relu<<<(N0 * 32 + 255) / 256, 256>>>(x, emb, ln_g, ln_b, N0);

    // 3. layer-1 aggregation (8 edges/warp)
    scatter_edges<<<(E1 + 63) / 64, 256>>>(h0, src1, dst1, agg1, cnt1, E1);

    // 4. layer-1 fused GEMM + relu -> h1
    sage_gemm<64, 1><<<(N1_C + 63) / 64, 256>>>(agg1, cnt1, h0, wt1, bl1, h1, N1_C);

    // 5. layer-2 aggregation
    scatter_edges<<<(E2 + 63) / 64, 256>>>(h1, src2, dst2, agg2, cnt2, E2);

    // 6. layer-2 fused GEMM -> d_out (TM=32 for more CTAs on small n)
    sage_gemm<32, 0><<<(N2_C + 31) / 32, 256>>>(agg2, cnt2, h1, wt2, bl2,
                                                (float*)d_out, N2_C);
}

// round 7
// speedup vs baseline: 1.4768x; 1.2394x over previous
#include <cuda_runtime.h>
#include <cstdint>

// ---------------- problem constants (fixed by the dataset) ----------------
#define IN_C   128
#define LEAF   50000
#define N0_MAX 100000
#define W_BAG  16
#define N1_C   25000
#define N2_C   5000

typedef unsigned long long u64;

// ---------------- device scratch (allocation-free rule) -------------------
__device__ float g_h0[(size_t)N0_MAX * IN_C];     // 51.2 MB  embed+LN+relu
__device__ float g_h1[(size_t)N1_C * IN_C];       // 12.8 MB  sage1 output (relu'd)
__device__ float g_agg1[(size_t)N1_C * IN_C];     // 12.8 MB
__device__ float g_agg2[(size_t)N2_C * IN_C];     //  2.6 MB
__device__ int   g_cnt1[N1_C];
__device__ int   g_cnt2[N2_C];
__device__ float g_Wt1[256 * 128];                // [k][t] combined (Wl|Wr) transposed
__device__ float g_Wt2[256 * 128];

// ---------------- f32x2 packed-FMA helpers ---------------------------------
__device__ __forceinline__ u64 pack2(float a) {
    u64 r;
    unsigned ai = __float_as_uint(a);
    asm("mov.b64 %0, {%1, %1};" : "=l"(r) : "r"(ai));
    return r;
}
__device__ __forceinline__ void fma2(u64& d, u64 a, u64 b) {
    asm("fma.rn.f32x2 %0, %1, %2, %0;" : "+l"(d) : "l"(a), "l"(b));
}
__device__ __forceinline__ void unpack2(u64 v, float& lo, float& hi) {
    unsigned l, h;
    asm("mov.b64 {%0, %1}, %2;" : "=r"(l), "=r"(h) : "l"(v));
    lo = __uint_as_float(l);
    hi = __uint_as_float(h);
}

// ---------------- zero accumulators + weight transpose (one launch) --------
__global__ void init_scratch(const float* __restrict__ Wl1, const float* __restrict__ Wr1,
                             const float* __restrict__ Wl2, const float* __restrict__ Wr2) {
    int i  = blockIdx.x * blockDim.x + threadIdx.x;
    int st = gridDim.x * blockDim.x;
    for (int j = i; j < N1_C * IN_C; j += st) g_agg1[j] = 0.f;
    for (int j = i; j < N2_C * IN_C; j += st) g_agg2[j] = 0.f;
    for (int j = i; j < N1_C; j += st) g_cnt1[j] = 0;
    for (int j = i; j < N2_C; j += st) g_cnt2[j] = 0;
    for (int j = i; j < 256 * 128; j += st) {
        int k = j >> 7;
        int t = j & 127;
        g_Wt1[j] = (k < 128) ? Wl1[t * 128 + k] : Wr1[t * 128 + (k - 128)];
        g_Wt2[j] = (k < 128) ? Wl2[t * 128 + k] : Wr2[t * 128 + (k - 128)];
    }
}

// ---------------- embedding bag sum + layernorm + relu ---------------------
__global__ void embed_ln_relu(const int* __restrict__ x, const float* __restrict__ emb,
                              const float* __restrict__ g, const float* __restrict__ b,
                              int N0) {
    int warp = (blockIdx.x * blockDim.x + threadIdx.x) >> 5;
    int lane = threadIdx.x & 31;
    if (warp >= N0) return;

    int idx_l = (lane < W_BAG) ? __ldg(x + (size_t)warp * W_BAG + lane) : 0;

    float4 a0 = make_float4(0.f, 0.f, 0.f, 0.f);
    float4 a1 = make_float4(0.f, 0.f, 0.f, 0.f);
#pragma unroll
    for (int w = 0; w < W_BAG; w += 2) {
        int i0 = __shfl_sync(0xffffffffu, idx_l, w);
        int i1 = __shfl_sync(0xffffffffu, idx_l, w + 1);
        float4 e0 = __ldg((const float4*)(emb + (size_t)i0 * IN_C + lane * 4));
        float4 e1 = __ldg((const float4*)(emb + (size_t)i1 * IN_C + lane * 4));
        a0.x += e0.x; a0.y += e0.y; a0.z += e0.z; a0.w += e0.w;
        a1.x += e1.x; a1.y += e1.y; a1.z += e1.z; a1.w += e1.w;
    }
    float4 acc;
    acc.x = a0.x + a1.x; acc.y = a0.y + a1.y;
    acc.z = a0.z + a1.z; acc.w = a0.w + a1.w;

    float s = acc.x + acc.y + acc.z + acc.w;
#pragma unroll
    for (int o = 16; o; o >>= 1) s += __shfl_xor_sync(0xffffffffu, s, o);
    float mu = s * (1.0f / 128.0f);
    float d0 = acc.x - mu, d1 = acc.y - mu, d2 = acc.z - mu, d3 = acc.w - mu;
    float q = d0 * d0 + d1 * d1 + d2 * d2 + d3 * d3;
#pragma unroll
    for (int o = 16; o; o >>= 1) q += __shfl_xor_sync(0xffffffffu, q, o);
    float rs = rsqrtf(q * (1.0f / 128.0f) + 1e-5f);

    float4 gg = __ldg((const float4*)(g + lane * 4));
    float4 bb = __ldg((const float4*)(b + lane * 4));
    float4 o4;
    o4.x = fmaxf(fmaf(d0 * rs, gg.x, bb.x), 0.f);
    o4.y = fmaxf(fmaf(d1 * rs, gg.y, bb.y), 0.f);
    o4.z = fmaxf(fmaf(d2 * rs, gg.z, bb.z), 0.f);
    o4.w = fmaxf(fmaf(d3 * rs, gg.w, bb.w), 0.f);
    *(float4*)(g_h0 + (size_t)warp * IN_C + lane * 4) = o4;
}

// ---------------- edge scatter-add (mean numerator + counts) ---------------
__global__ void scatter_edges(const float* __restrict__ h, const int* __restrict__ src,
                              const int* __restrict__ dst, float* __restrict__ agg,
                              int* __restrict__ cnt, int E) {
    int warp = (blockIdx.x * blockDim.x + threadIdx.x) >> 5;
    int lane = threadIdx.x & 31;
    int e0 = warp * 8;
    if (e0 >= E) return;

    if (e0 + 8 <= E) {
        int4 sa = __ldg((const int4*)(src + e0));
        int4 sb = __ldg((const int4*)(src + e0 + 4));
        int4 da = __ldg((const int4*)(dst + e0));
        int4 db = __ldg((const int4*)(dst + e0 + 4));
        int s[8] = {sa.x, sa.y, sa.z, sa.w, sb.x, sb.y, sb.z, sb.w};
        int d[8] = {da.x, da.y, da.z, da.w, db.x, db.y, db.z, db.w};
        float4 v[8];
#pragma unroll
        for (int j = 0; j < 8; ++j)
            v[j] = __ldg((const float4*)(h + (size_t)s[j] * IN_C + lane * 4));
#pragma unroll
        for (int j = 0; j < 8; ++j) {
            float* p = agg + (size_t)d[j] * IN_C + lane * 4;
            asm volatile("red.global.add.v4.f32 [%0], {%1,%2,%3,%4};"
                         :: "l"(p), "f"(v[j].x), "f"(v[j].y), "f"(v[j].z), "f"(v[j].w)
                         : "memory");
        }
        if (lane < 8) {
            int dd = (lane == 0) ? da.x : (lane == 1) ? da.y : (lane == 2) ? da.z :
                     (lane == 3) ? da.w : (lane == 4) ? db.x : (lane == 5) ? db.y :
                     (lane == 6) ? db.z : db.w;
            asm volatile("red.global.add.u32 [%0], %1;" :: "l"(cnt + dd), "r"(1) : "memory");
        }
    } else {
        for (int e = e0; e < E; ++e) {
            int s = __ldg(src + e);
            int d = __ldg(dst + e);
            float4 v = __ldg((const float4*)(h + (size_t)s * IN_C + lane * 4));
            float* p = agg + (size_t)d * IN_C + lane * 4;
            asm volatile("red.global.add.v4.f32 [%0], {%1,%2,%3,%4};"
                         :: "l"(p), "f"(v.x), "f"(v.y), "f"(v.z), "f"(v.w)
                         : "memory");
            if (lane == 0)
                asm volatile("red.global.add.u32 [%0], %1;" :: "l"(cnt + d), "r"(1) : "memory");
        }
    }
}

// ---------------- fused SAGE GEMM: out = mean@Wl^T + bl + self@Wr^T (+relu)
// A = [mean | self] is [n, 256]; Wt is [256, 128] ([k][t]).
// Tile: TM rows x 64 cols per CTA (gridDim.y = 2 column blocks -> 2x grid).
// 256 threads, thread tile (TM/16) x 4, packed f32x2 FMAs.
// Register-staged smem double buffer: 1 barrier per 32-k chunk.
template<int TM, int DO_RELU>
__global__ __launch_bounds__(256)
void sage_gemm(const float* __restrict__ agg, const int* __restrict__ cnt,
               const float* __restrict__ selfh, const float* __restrict__ Wt,
               const float* __restrict__ bias, float* __restrict__ out, int n) {
    constexpr int RPT = TM / 16;   // output rows per thread
    constexpr int ALD = TM / 8;    // A elements per thread per chunk

    __shared__ float  As[2][TM][34];      // stride 34: float2 @ even kk stays 8B-aligned
    __shared__ float4 Ws4[2][32][16];     // [kk][c/4], 64 cols
    __shared__ float  rinv[TM];

    int tid  = threadIdx.x;
    int row0 = blockIdx.x * TM;
    int col0 = blockIdx.y * 64;
    int tx = tid & 15;       // col group (4 cols)
    int ty = tid >> 4;       // row group (RPT rows)

    if (tid < TM) {
        int r = row0 + tid;
        rinv[tid] = (r < n) ? (1.0f / fmaxf((float)__ldg(cnt + r), 1.0f)) : 0.0f;
    }
    __syncthreads();   // rinv visible to all A-tile loaders

    int kk    = tid & 31;
    int rbase = tid >> 5;

    float  a_reg[ALD];
    float4 w_reg[2];

    auto load_chunk = [&](int c) {
#pragma unroll
        for (int i = 0; i < ALD; ++i) {
            int rr = rbase + i * 8;
            int r  = row0 + rr;
            float v = 0.f;
            if (r < n) {
                if (c < 4) v = agg[(size_t)r * 128 + c * 32 + kk] * rinv[rr];
                else       v = selfh[(size_t)r * 128 + (c - 4) * 32 + kk];
            }
            a_reg[i] = v;
        }
#pragma unroll
        for (int i = 0; i < 2; ++i) {
            int idx = tid + i * 256;
            int wk = idx >> 4, c4 = idx & 15;
            w_reg[i] = *(const float4*)(Wt + (size_t)(c * 32 + wk) * 128 + col0 + c4 * 4);
        }
    };
    auto store_chunk = [&](int buf) {
#pragma unroll
        for (int i = 0; i < ALD; ++i)
            As[buf][rbase + i * 8][kk] = a_reg[i];
#pragma unroll
        for (int i = 0; i < 2; ++i) {
            int idx = tid + i * 256;
            Ws4[buf][idx >> 4][idx & 15] = w_reg[i];
        }
    };

    u64 accp[RPT][2];
#pragma unroll
    for (int r = 0; r < RPT; ++r) {
        accp[r][0] = 0ull;
        accp[r][1] = 0ull;
    }

    load_chunk(0);
    store_chunk(0);
    __syncthreads();

#pragma unroll
    for (int c = 0; c < 8; ++c) {
        if (c < 7) load_chunk(c + 1);      // global -> regs, overlaps compute
        int buf = c & 1;
#pragma unroll
        for (int k2 = 0; k2 < 32; k2 += 2) {
            u64 ap0[RPT], ap1[RPT];
#pragma unroll
            for (int r = 0; r < RPT; ++r) {
                float2 a2 = *(const float2*)&As[buf][ty * RPT + r][k2];
                ap0[r] = pack2(a2.x);
                ap1[r] = pack2(a2.y);
            }
            ulonglong2 wa = *(const ulonglong2*)&Ws4[buf][k2][tx];
            ulonglong2 wb = *(const ulonglong2*)&Ws4[buf][k2 + 1][tx];
#pragma unroll
            for (int r = 0; r < RPT; ++r) {
                fma2(accp[r][0], ap0[r], wa.x);
                fma2(accp[r][1], ap0[r], wa.y);
                fma2(accp[r][0], ap1[r], wb.x);
                fma2(accp[r][1], ap1[r], wb.y);
            }
        }
        if (c < 7) store_chunk((c + 1) & 1);  // other buffer; prev reads done
        __syncthreads();
    }

    // epilogue: unpack, bias (+relu), vectorized store
    float4 bb = __ldg((const float4*)(bias + col0 + tx * 4));
#pragma unroll
    for (int r = 0; r < RPT; ++r) {
        int row = row0 + ty * RPT + r;
        if (row >= n) continue;
        float f[4];
        unpack2(accp[r][0], f[0], f[1]);
        unpack2(accp[r][1], f[2], f[3]);
        float4 o;
        o.x = f[0] + bb.x;
        o.y = f[1] + bb.y;
        o.z = f[2] + bb.z;
        o.w = f[3] + bb.w;
        if (DO_RELU) {
            o.x = fmaxf(o.x, 0.f); o.y = fmaxf(o.y, 0.f);
            o.z = fmaxf(o.z, 0.f); o.w = fmaxf(o.w, 0.f);
        }
        *(float4*)(out + (size_t)row * 128 + col0 + tx * 4) = o;
    }
}

// ---------------- host launcher --------------------------------------------
extern "C" void kernel_launch(void* const* d_in, const int* in_sizes, int n_in,
                              void* d_out, int out_size) {
    int ix = 0, is1 = 1, id1 = 2, is2 = 3, id2 = 4;
    int iemb, ig, ib, iwl1, ibl1, iwr1, iwl2, ibl2, iwr2;
    if (n_in >= 16) {
        iemb = 7; ig = 8; ib = 9; iwl1 = 10; ibl1 = 11; iwr1 = 12;
        iwl2 = 13; ibl2 = 14; iwr2 = 15;
    } else {
        iemb = 5; ig = 6; ib = 7; iwl1 = 8; ibl1 = 9; iwr1 = 10;
        iwl2 = 11; ibl2 = 12; iwr2 = 13;
    }

    const int*   x    = (const int*)d_in[ix];
    const int*   src1 = (const int*)d_in[is1];
    const int*   dst1 = (const int*)d_in[id1];
    const int*   src2 = (const int*)d_in[is2];
    const int*   dst2 = (const int*)d_in[id2];
    const float* emb  = (const float*)d_in[iemb];
    const float* ln_g = (const float*)d_in[ig];
    const float* ln_b = (const float*)d_in[ib];
    const float* Wl1  = (const float*)d_in[iwl1];
    const float* bl1  = (const float*)d_in[ibl1];
    const float* Wr1  = (const float*)d_in[iwr1];
    const float* Wl2  = (const float*)d_in[iwl2];
    const float* bl2  = (const float*)d_in[ibl2];
    const float* Wr2  = (const float*)d_in[iwr2];

    int N0 = in_sizes[ix] / W_BAG;
    int E1 = in_sizes[is1];
    int E2 = in_sizes[is2];

    float *h0, *h1, *agg1, *agg2, *wt1, *wt2;
    int *cnt1, *cnt2;
    cudaGetSymbolAddress((void**)&h0,   g_h0);
    cudaGetSymbolAddress((void**)&h1,   g_h1);
    cudaGetSymbolAddress((void**)&agg1, g_agg1);
    cudaGetSymbolAddress((void**)&agg2, g_agg2);
    cudaGetSymbolAddress((void**)&cnt1, g_cnt1);
    cudaGetSymbolAddress((void**)&cnt2, g_cnt2);
    cudaGetSymbolAddress((void**)&wt1,  g_Wt1);
    cudaGetSymbolAddress((void**)&wt2,  g_Wt2);

    // 1. zero accumulators + weight transpose (single launch)
    init_scratch<<<512, 256>>>(Wl1, Wr1, Wl2, Wr2);

    // 2. embedding bag + LN + relu -> h0  (one warp per row)
    embed_ln_relu<<<(N0 * 32 + 255) / 256, 256>>>(x, emb, ln_g, ln_b, N0);

    // 3. layer-1 aggregation (8 edges/warp)
    scatter_edges<<<(E1 + 63) / 64, 256>>>(h0, src1, dst1, agg1, cnt1, E1);

    // 4. layer-1 fused GEMM + relu -> h1 (64x64 tiles, 2 col-blocks)
    {
        dim3 grid((N1_C + 63) / 64, 2);
        sage_gemm<64, 1><<<grid, 256>>>(agg1, cnt1, h0, wt1, bl1, h1, N1_C);
    }

    // 5. layer-2 aggregation
    scatter_edges<<<(E2 + 63) / 64, 256>>>(h1, src2, dst2, agg2, cnt2, E2);

    // 6. layer-2 fused GEMM -> d_out (32x64 tiles, 2 col-blocks)
    {
        dim3 grid((N2_C + 31) / 32, 2);
        sage_gemm<32, 0><<<grid, 256>>>(agg2, cnt2, h1, wt2, bl2,
                                        (float*)d_out, N2_C);
    }
}

// round 8
// speedup vs baseline: 1.9595x; 1.3268x over previous
#include <cuda_runtime.h>
#include <cstdint>

// ---------------- problem constants (fixed by the dataset) ----------------
#define IN_C   128
#define LEAF   50000
#define N0_MAX 100000
#define W_BAG  16
#define N1_C   25000
#define N2_C   5000

typedef unsigned long long u64;

// ---------------- device scratch (allocation-free rule) -------------------
__device__ float g_h0[(size_t)N0_MAX * IN_C];     // 51.2 MB  embed+LN+relu
__device__ float g_h1[(size_t)N1_C * IN_C];       // 12.8 MB  sage1 output (relu'd)
__device__ float g_agg1[(size_t)N1_C * IN_C];     // 12.8 MB
__device__ float g_agg2[(size_t)N2_C * IN_C];     //  2.6 MB
__device__ int   g_cnt1[N1_C];
__device__ int   g_cnt2[N2_C];
__device__ float g_Wt1[256 * 128];                // [k][t] combined (Wl|Wr), tf32-rounded
__device__ float g_Wt2[256 * 128];

// ---------------- small asm helpers ----------------------------------------
__device__ __forceinline__ unsigned cvt_tf32(float x) {
    unsigned u;
    asm("cvt.rna.tf32.f32 %0, %1;" : "=r"(u) : "f"(x));
    return u;
}
__device__ __forceinline__ void mma_tf32(float* d, const unsigned* a, const unsigned* b) {
    asm volatile(
        "mma.sync.aligned.m16n8k8.row.col.f32.tf32.tf32.f32 "
        "{%0,%1,%2,%3}, {%4,%5,%6,%7}, {%8,%9}, {%0,%1,%2,%3};"
        : "+f"(d[0]), "+f"(d[1]), "+f"(d[2]), "+f"(d[3])
        : "r"(a[0]), "r"(a[1]), "r"(a[2]), "r"(a[3]), "r"(b[0]), "r"(b[1]));
}
__device__ __forceinline__ void cp16(unsigned smem_dst, const void* gsrc, bool pred) {
    int sz = pred ? 16 : 0;
    asm volatile("cp.async.cg.shared.global [%0], [%1], 16, %2;"
                 :: "r"(smem_dst), "l"(gsrc), "r"(sz));
}
__device__ __forceinline__ void cp_commit() {
    asm volatile("cp.async.commit_group;");
}
__device__ __forceinline__ void cp_wait0() {
    asm volatile("cp.async.wait_group 0;");
}

// ---------------- zero accumulators + weight transpose/round (one launch) --
__global__ void init_scratch(const float* __restrict__ Wl1, const float* __restrict__ Wr1,
                             const float* __restrict__ Wl2, const float* __restrict__ Wr2) {
    int i  = blockIdx.x * blockDim.x + threadIdx.x;
    int st = gridDim.x * blockDim.x;
    for (int j = i; j < N1_C * IN_C; j += st) g_agg1[j] = 0.f;
    for (int j = i; j < N2_C * IN_C; j += st) g_agg2[j] = 0.f;
    for (int j = i; j < N1_C; j += st) g_cnt1[j] = 0;
    for (int j = i; j < N2_C; j += st) g_cnt2[j] = 0;
    for (int j = i; j < 256 * 128; j += st) {
        int k = j >> 7;
        int t = j & 127;
        float w1 = (k < 128) ? Wl1[t * 128 + k] : Wr1[t * 128 + (k - 128)];
        float w2 = (k < 128) ? Wl2[t * 128 + k] : Wr2[t * 128 + (k - 128)];
        g_Wt1[j] = __uint_as_float(cvt_tf32(w1));   // pre-rounded to tf32
        g_Wt2[j] = __uint_as_float(cvt_tf32(w2));
    }
}

// ---------------- embedding bag sum + layernorm + relu ---------------------
__global__ void embed_ln_relu(const int* __restrict__ x, const float* __restrict__ emb,
                              const float* __restrict__ g, const float* __restrict__ b,
                              int N0) {
    int warp = (blockIdx.x * blockDim.x + threadIdx.x) >> 5;
    int lane = threadIdx.x & 31;
    if (warp >= N0) return;

    int idx_l = (lane < W_BAG) ? __ldg(x + (size_t)warp * W_BAG + lane) : 0;

    float4 a0 = make_float4(0.f, 0.f, 0.f, 0.f);
    float4 a1 = make_float4(0.f, 0.f, 0.f, 0.f);
#pragma unroll
    for (int w = 0; w < W_BAG; w += 2) {
        int i0 = __shfl_sync(0xffffffffu, idx_l, w);
        int i1 = __shfl_sync(0xffffffffu, idx_l, w + 1);
        float4 e0 = __ldg((const float4*)(emb + (size_t)i0 * IN_C + lane * 4));
        float4 e1 = __ldg((const float4*)(emb + (size_t)i1 * IN_C + lane * 4));
        a0.x += e0.x; a0.y += e0.y; a0.z += e0.z; a0.w += e0.w;
        a1.x += e1.x; a1.y += e1.y; a1.z += e1.z; a1.w += e1.w;
    }
    float4 acc;
    acc.x = a0.x + a1.x; acc.y = a0.y + a1.y;
    acc.z = a0.z + a1.z; acc.w = a0.w + a1.w;

    float s = acc.x + acc.y + acc.z + acc.w;
#pragma unroll
    for (int o = 16; o; o >>= 1) s += __shfl_xor_sync(0xffffffffu, s, o);
    float mu = s * (1.0f / 128.0f);
    float d0 = acc.x - mu, d1 = acc.y - mu, d2 = acc.z - mu, d3 = acc.w - mu;
    float q = d0 * d0 + d1 * d1 + d2 * d2 + d3 * d3;
#pragma unroll
    for (int o = 16; o; o >>= 1) q += __shfl_xor_sync(0xffffffffu, q, o);
    float rs = rsqrtf(q * (1.0f / 128.0f) + 1e-5f);

    float4 gg = __ldg((const float4*)(g + lane * 4));
    float4 bb = __ldg((const float4*)(b + lane * 4));
    float4 o4;
    o4.x = fmaxf(fmaf(d0 * rs, gg.x, bb.x), 0.f);
    o4.y = fmaxf(fmaf(d1 * rs, gg.y, bb.y), 0.f);
    o4.z = fmaxf(fmaf(d2 * rs, gg.z, bb.z), 0.f);
    o4.w = fmaxf(fmaf(d3 * rs, gg.w, bb.w), 0.f);
    *(float4*)(g_h0 + (size_t)warp * IN_C + lane * 4) = o4;
}

// ---------------- edge scatter-add (mean numerator + counts) ---------------
__global__ void scatter_edges(const float* __restrict__ h, const int* __restrict__ src,
                              const int* __restrict__ dst, float* __restrict__ agg,
                              int* __restrict__ cnt, int E) {
    int warp = (blockIdx.x * blockDim.x + threadIdx.x) >> 5;
    int lane = threadIdx.x & 31;
    int e0 = warp * 8;
    if (e0 >= E) return;

    if (e0 + 8 <= E) {
        int4 sa = __ldg((const int4*)(src + e0));
        int4 sb = __ldg((const int4*)(src + e0 + 4));
        int4 da = __ldg((const int4*)(dst + e0));
        int4 db = __ldg((const int4*)(dst + e0 + 4));
        int s[8] = {sa.x, sa.y, sa.z, sa.w, sb.x, sb.y, sb.z, sb.w};
        int d[8] = {da.x, da.y, da.z, da.w, db.x, db.y, db.z, db.w};
        float4 v[8];
#pragma unroll
        for (int j = 0; j < 8; ++j)
            v[j] = __ldg((const float4*)(h + (size_t)s[j] * IN_C + lane * 4));
#pragma unroll
        for (int j = 0; j < 8; ++j) {
            float* p = agg + (size_t)d[j] * IN_C + lane * 4;
            asm volatile("red.global.add.v4.f32 [%0], {%1,%2,%3,%4};"
                         :: "l"(p), "f"(v[j].x), "f"(v[j].y), "f"(v[j].z), "f"(v[j].w)
                         : "memory");
        }
        if (lane < 8) {
            int dd = (lane == 0) ? da.x : (lane == 1) ? da.y : (lane == 2) ? da.z :
                     (lane == 3) ? da.w : (lane == 4) ? db.x : (lane == 5) ? db.y :
                     (lane == 6) ? db.z : db.w;
            asm volatile("red.global.add.u32 [%0], %1;" :: "l"(cnt + dd), "r"(1) : "memory");
        }
    } else {
        for (int e = e0; e < E; ++e) {
            int s = __ldg(src + e);
            int d = __ldg(dst + e);
            float4 v = __ldg((const float4*)(h + (size_t)s * IN_C + lane * 4));
            float* p = agg + (size_t)d * IN_C + lane * 4;
            asm volatile("red.global.add.v4.f32 [%0], {%1,%2,%3,%4};"
                         :: "l"(p), "f"(v.x), "f"(v.y), "f"(v.z), "f"(v.w)
                         : "memory");
            if (lane == 0)
                asm volatile("red.global.add.u32 [%0], %1;" :: "l"(cnt + d), "r"(1) : "memory");
        }
    }
}

// ---------------- tensor-core fused SAGE GEMM -------------------------------
// out[n,128] = (agg*rinv)[n,128] @ Wl^T + bias + self[n,128] @ Wr^T (+relu)
// A = [mean | self] logically [n,256]; Wt is [256,128] ([k][t]), tf32-rounded.
// 128 threads = 4 warps (2M x 2N); warp tile = (MFRAG*16) x 64.
// CTA tile = (MFRAG*32) x 128. K chunks of 32, cp.async double-buffered.
// mma.sync.m16n8k8 tf32, fp32 accumulate. rinv folded at A-fragment load.
template<int MFRAG, int DO_RELU>
__global__ __launch_bounds__(128)
void sage_gemm_tc(const float* __restrict__ agg, const int* __restrict__ cnt,
                  const float* __restrict__ selfh, const float* __restrict__ Wt,
                  const float* __restrict__ bias, float* __restrict__ out, int n) {
    constexpr int TM = MFRAG * 32;

    __shared__ float As[2][TM][36];    // banks: 4g+tig -> conflict-free frag loads
    __shared__ float Ws[2][32][136];   // banks: 8tig+g -> conflict-free frag loads
    __shared__ float rinv_s[TM];

    int tid  = threadIdx.x;
    int lane = tid & 31;
    int w    = tid >> 5;
    int g    = lane >> 2;      // groupID 0..7
    int tig  = lane & 3;       // thread-in-group 0..3
    int wm   = w >> 1;         // 0..1  (M split)
    int wn   = w & 1;          // 0..1  (N split)
    int row0 = blockIdx.x * TM;

    if (tid < TM) {
        int r = row0 + tid;
        rinv_s[tid] = (r < n) ? (1.0f / fmaxf((float)__ldg(cnt + r), 1.0f)) : 0.0f;
    }
    __syncthreads();

    // per-thread rinv for fragment rows (local row index)
    float rv[MFRAG][2];
#pragma unroll
    for (int mf = 0; mf < MFRAG; ++mf) {
        int rl = wm * MFRAG * 16 + mf * 16 + g;
        rv[mf][0] = rinv_s[rl];
        rv[mf][1] = rinv_s[rl + 8];
    }

    auto copyA = [&](int c, int buf) {
        const float* base = (c < 4) ? agg : selfh;
        int kOff = (c & 3) * 32;
#pragma unroll
        for (int i = 0; i < TM / 16; ++i) {
            int idx = tid + i * 128;
            int r = idx >> 3, seg = idx & 7;
            const float* src = base + (size_t)(row0 + r) * 128 + kOff + seg * 4;
            cp16((unsigned)__cvta_generic_to_shared(&As[buf][r][seg * 4]),
                 src, (row0 + r) < n);
        }
    };
    auto copyW = [&](int c, int buf) {
#pragma unroll
        for (int i = 0; i < 8; ++i) {
            int idx = tid + i * 128;
            int r = idx >> 5, seg = idx & 31;
            const float* src = Wt + (size_t)(c * 32 + r) * 128 + seg * 4;
            cp16((unsigned)__cvta_generic_to_shared(&Ws[buf][r][seg * 4]),
                 src, true);
        }
    };

    float acc[MFRAG][8][4];
#pragma unroll
    for (int mf = 0; mf < MFRAG; ++mf)
#pragma unroll
        for (int nt = 0; nt < 8; ++nt)
#pragma unroll
            for (int q = 0; q < 4; ++q) acc[mf][nt][q] = 0.f;

    copyA(0, 0); copyW(0, 0); cp_commit();

#pragma unroll
    for (int c = 0; c < 8; ++c) {
        int buf = c & 1;
        cp_wait0();
        __syncthreads();                       // chunk c visible; buf^1 reads done
        if (c < 7) { copyA(c + 1, buf ^ 1); copyW(c + 1, buf ^ 1); cp_commit(); }

        float s0[MFRAG], s1[MFRAG];
#pragma unroll
        for (int mf = 0; mf < MFRAG; ++mf) {
            s0[mf] = (c < 4) ? rv[mf][0] : 1.0f;
            s1[mf] = (c < 4) ? rv[mf][1] : 1.0f;
        }

#pragma unroll
        for (int ks = 0; ks < 4; ++ks) {
            int kk = ks * 8;
            unsigned a[MFRAG][4];
#pragma unroll
            for (int mf = 0; mf < MFRAG; ++mf) {
                int r0 = wm * MFRAG * 16 + mf * 16 + g;
                a[mf][0] = cvt_tf32(As[buf][r0][kk + tig]         * s0[mf]);
                a[mf][1] = cvt_tf32(As[buf][r0 + 8][kk + tig]     * s1[mf]);
                a[mf][2] = cvt_tf32(As[buf][r0][kk + tig + 4]     * s0[mf]);
                a[mf][3] = cvt_tf32(As[buf][r0 + 8][kk + tig + 4] * s1[mf]);
            }
            unsigned b[8][2];
#pragma unroll
            for (int nt = 0; nt < 8; ++nt) {
                int ncol = wn * 64 + nt * 8 + g;
                b[nt][0] = __float_as_uint(Ws[buf][kk + tig][ncol]);      // pre-rounded
                b[nt][1] = __float_as_uint(Ws[buf][kk + tig + 4][ncol]);
            }
#pragma unroll
            for (int mf = 0; mf < MFRAG; ++mf)
#pragma unroll
                for (int nt = 0; nt < 8; ++nt)
                    mma_tf32(acc[mf][nt], a[mf], b[nt]);
        }
    }

    // epilogue: bias (+relu), float2 stores
#pragma unroll
    for (int mf = 0; mf < MFRAG; ++mf) {
        int rbase = row0 + wm * MFRAG * 16 + mf * 16 + g;
#pragma unroll
        for (int nt = 0; nt < 8; ++nt) {
            int cl = wn * 64 + nt * 8 + tig * 2;
            float2 bb = __ldg((const float2*)(bias + cl));
            float2 o0, o1;
            o0.x = acc[mf][nt][0] + bb.x;
            o0.y = acc[mf][nt][1] + bb.y;
            o1.x = acc[mf][nt][2] + bb.x;
            o1.y = acc[mf][nt][3] + bb.y;
            if (DO_RELU) {
                o0.x = fmaxf(o0.x, 0.f); o0.y = fmaxf(o0.y, 0.f);
                o1.x = fmaxf(o1.x, 0.f); o1.y = fmaxf(o1.y, 0.f);
            }
            if (rbase < n)
                *(float2*)(out + (size_t)rbase * 128 + cl) = o0;
            if (rbase + 8 < n)
                *(float2*)(out + (size_t)(rbase + 8) * 128 + cl) = o1;
        }
    }
}

// ---------------- host launcher --------------------------------------------
extern "C" void kernel_launch(void* const* d_in, const int* in_sizes, int n_in,
                              void* d_out, int out_size) {
    int ix = 0, is1 = 1, id1 = 2, is2 = 3, id2 = 4;
    int iemb, ig, ib, iwl1, ibl1, iwr1, iwl2, ibl2, iwr2;
    if (n_in >= 16) {
        iemb = 7; ig = 8; ib = 9; iwl1 = 10; ibl1 = 11; iwr1 = 12;
        iwl2 = 13; ibl2 = 14; iwr2 = 15;
    } else {
        iemb = 5; ig = 6; ib = 7; iwl1 = 8; ibl1 = 9; iwr1 = 10;
        iwl2 = 11; ibl2 = 12; iwr2 = 13;
    }

    const int*   x    = (const int*)d_in[ix];
    const int*   src1 = (const int*)d_in[is1];
    const int*   dst1 = (const int*)d_in[id1];
    const int*   src2 = (const int*)d_in[is2];
    const int*   dst2 = (const int*)d_in[id2];
    const float* emb  = (const float*)d_in[iemb];
    const float* ln_g = (const float*)d_in[ig];
    const float* ln_b = (const float*)d_in[ib];
    const float* Wl1  = (const float*)d_in[iwl1];
    const float* bl1  = (const float*)d_in[ibl1];
    const float* Wr1  = (const float*)d_in[iwr1];
    const float* Wl2  = (const float*)d_in[iwl2];
    const float* bl2  = (const float*)d_in[ibl2];
    const float* Wr2  = (const float*)d_in[iwr2];

    int N0 = in_sizes[ix] / W_BAG;
    int E1 = in_sizes[is1];
    int E2 = in_sizes[is2];

    float *h0, *h1, *agg1, *agg2, *wt1, *wt2;
    int *cnt1, *cnt2;
    cudaGetSymbolAddress((void**)&h0,   g_h0);
    cudaGetSymbolAddress((void**)&h1,   g_h1);
    cudaGetSymbolAddress((void**)&agg1, g_agg1);
    cudaGetSymbolAddress((void**)&agg2, g_agg2);
    cudaGetSymbolAddress((void**)&cnt1, g_cnt1);
    cudaGetSymbolAddress((void**)&cnt2, g_cnt2);
    cudaGetSymbolAddress((void**)&wt1,  g_Wt1);
    cudaGetSymbolAddress((void**)&wt2,  g_Wt2);

    // 1. zero accumulators + tf32-rounded weight transpose
    init_scratch<<<512, 256>>>(Wl1, Wr1, Wl2, Wr2);

    // 2. embedding bag + LN + relu -> h0  (one warp per row)
    embed_ln_relu<<<(N0 * 32 + 255) / 256, 256>>>(x, emb, ln_g, ln_b, N0);

    // 3. layer-1 aggregation (8 edges/warp)
    scatter_edges<<<(E1 + 63) / 64, 256>>>(h0, src1, dst1, agg1, cnt1, E1);

    // 4. layer-1 fused tensor-core GEMM + relu -> h1 (64x128 tiles)
    sage_gemm_tc<2, 1><<<(N1_C + 63) / 64, 128>>>(agg1, cnt1, h0, wt1, bl1, h1, N1_C);

    // 5. layer-2 aggregation
    scatter_edges<<<(E2 + 63) / 64, 256>>>(h1, src2, dst2, agg2, cnt2, E2);

    // 6. layer-2 fused tensor-core GEMM -> d_out (32x128 tiles)
    sage_gemm_tc<1, 0><<<(N2_C + 31) / 32, 128>>>(agg2, cnt2, h1, wt2, bl2,
                                                  (float*)d_out, N2_C);
}

// round 9
// speedup vs baseline: 1.9933x; 1.0172x over previous
#include <cuda_runtime.h>
#include <cuda_fp16.h>
#include <cstdint>

// ---------------- problem constants (fixed by the dataset) ----------------
#define IN_C   128
#define LEAF   50000
#define N0_MAX 100000
#define W_BAG  16
#define N1_C   25000
#define N2_C   5000

typedef unsigned long long u64;

// ---------------- device scratch (allocation-free rule) -------------------
__device__ float  g_h0 [(size_t)N0_MAX * IN_C];   // 51.2 MB fp32 h0 (gemm self path)
__device__ __half g_h0h[(size_t)N0_MAX * IN_C];   // 25.6 MB fp16 h0 (scatter gather)
__device__ float  g_h1 [(size_t)N1_C * IN_C];     // 12.8 MB fp32 h1
__device__ __half g_h1h[(size_t)N1_C * IN_C];     //  6.4 MB fp16 h1 (scatter gather)
__device__ __half g_embh[(size_t)LEAF * IN_C];    // 12.8 MB fp16 emb table
__device__ float  g_agg1[(size_t)N1_C * IN_C];    // 12.8 MB
__device__ float  g_agg2[(size_t)N2_C * IN_C];    //  2.6 MB
__device__ int    g_cnt1[N1_C];
__device__ int    g_cnt2[N2_C];
__device__ float  g_Wt1[256 * 128];               // [k][t] combined (Wl|Wr), tf32-rounded
__device__ float  g_Wt2[256 * 128];

// ---------------- small asm helpers ----------------------------------------
__device__ __forceinline__ unsigned cvt_tf32(float x) {
    unsigned u;
    asm("cvt.rna.tf32.f32 %0, %1;" : "=r"(u) : "f"(x));
    return u;
}
__device__ __forceinline__ void mma_tf32(float* d, const unsigned* a, const unsigned* b) {
    asm volatile(
        "mma.sync.aligned.m16n8k8.row.col.f32.tf32.tf32.f32 "
        "{%0,%1,%2,%3}, {%4,%5,%6,%7}, {%8,%9}, {%0,%1,%2,%3};"
        : "+f"(d[0]), "+f"(d[1]), "+f"(d[2]), "+f"(d[3])
        : "r"(a[0]), "r"(a[1]), "r"(a[2]), "r"(a[3]), "r"(b[0]), "r"(b[1]));
}
__device__ __forceinline__ void cp16(unsigned smem_dst, const void* gsrc, bool pred) {
    int sz = pred ? 16 : 0;
    asm volatile("cp.async.cg.shared.global [%0], [%1], 16, %2;"
                 :: "r"(smem_dst), "l"(gsrc), "r"(sz));
}
__device__ __forceinline__ void cp_commit() {
    asm volatile("cp.async.commit_group;");
}
__device__ __forceinline__ void cp_wait0() {
    asm volatile("cp.async.wait_group 0;");
}

// 4 halves -> float4 (8B load)
__device__ __forceinline__ float4 ld_half4(const __half* p) {
    uint2 r = __ldg((const uint2*)p);
    __half2 a = *reinterpret_cast<__half2*>(&r.x);
    __half2 b = *reinterpret_cast<__half2*>(&r.y);
    float2 fa = __half22float2(a), fb = __half22float2(b);
    return make_float4(fa.x, fa.y, fb.x, fb.y);
}
// float4 -> 4 halves (8B store)
__device__ __forceinline__ void st_half4(__half* p, float4 v) {
    __half2 a = __floats2half2_rn(v.x, v.y);
    __half2 b = __floats2half2_rn(v.z, v.w);
    uint2 r;
    r.x = *reinterpret_cast<unsigned*>(&a);
    r.y = *reinterpret_cast<unsigned*>(&b);
    *(uint2*)p = r;
}

// ---------------- init: zero acc + weight prep + emb fp16 conversion -------
__global__ void init_scratch(const float* __restrict__ Wl1, const float* __restrict__ Wr1,
                             const float* __restrict__ Wl2, const float* __restrict__ Wr2,
                             const float* __restrict__ emb) {
    int i  = blockIdx.x * blockDim.x + threadIdx.x;
    int st = gridDim.x * blockDim.x;
    for (int j = i; j < N1_C * IN_C; j += st) g_agg1[j] = 0.f;
    for (int j = i; j < N2_C * IN_C; j += st) g_agg2[j] = 0.f;
    for (int j = i; j < N1_C; j += st) g_cnt1[j] = 0;
    for (int j = i; j < N2_C; j += st) g_cnt2[j] = 0;
    for (int j = i; j < 256 * 128; j += st) {
        int k = j >> 7;
        int t = j & 127;
        float w1 = (k < 128) ? Wl1[t * 128 + k] : Wr1[t * 128 + (k - 128)];
        float w2 = (k < 128) ? Wl2[t * 128 + k] : Wr2[t * 128 + (k - 128)];
        g_Wt1[j] = __uint_as_float(cvt_tf32(w1));   // pre-rounded to tf32
        g_Wt2[j] = __uint_as_float(cvt_tf32(w2));
    }
    // emb fp32 -> fp16 (float4 granularity: 6.4M elems = 1.6M float4)
    for (int j = i; j < LEAF * IN_C / 4; j += st) {
        float4 v = __ldg((const float4*)(emb + (size_t)j * 4));
        st_half4(g_embh + (size_t)j * 4, v);
    }
}

// ---------------- embedding bag sum + layernorm + relu (fp16 gather) -------
// one warp per row; lane owns channels 4l..4l+3 (8B fp16 loads).
__global__ void embed_ln_relu(const int* __restrict__ x, const float* __restrict__ g,
                              const float* __restrict__ b, int N0) {
    int warp = (blockIdx.x * blockDim.x + threadIdx.x) >> 5;
    int lane = threadIdx.x & 31;
    if (warp >= N0) return;

    int idx_l = (lane < W_BAG) ? __ldg(x + (size_t)warp * W_BAG + lane) : 0;

    float4 a0 = make_float4(0.f, 0.f, 0.f, 0.f);
    float4 a1 = make_float4(0.f, 0.f, 0.f, 0.f);
#pragma unroll
    for (int w = 0; w < W_BAG; w += 2) {
        int i0 = __shfl_sync(0xffffffffu, idx_l, w);
        int i1 = __shfl_sync(0xffffffffu, idx_l, w + 1);
        float4 e0 = ld_half4(g_embh + (size_t)i0 * IN_C + lane * 4);
        float4 e1 = ld_half4(g_embh + (size_t)i1 * IN_C + lane * 4);
        a0.x += e0.x; a0.y += e0.y; a0.z += e0.z; a0.w += e0.w;
        a1.x += e1.x; a1.y += e1.y; a1.z += e1.z; a1.w += e1.w;
    }
    float4 acc;
    acc.x = a0.x + a1.x; acc.y = a0.y + a1.y;
    acc.z = a0.z + a1.z; acc.w = a0.w + a1.w;

    float s = acc.x + acc.y + acc.z + acc.w;
#pragma unroll
    for (int o = 16; o; o >>= 1) s += __shfl_xor_sync(0xffffffffu, s, o);
    float mu = s * (1.0f / 128.0f);
    float d0 = acc.x - mu, d1 = acc.y - mu, d2 = acc.z - mu, d3 = acc.w - mu;
    float q = d0 * d0 + d1 * d1 + d2 * d2 + d3 * d3;
#pragma unroll
    for (int o = 16; o; o >>= 1) q += __shfl_xor_sync(0xffffffffu, q, o);
    float rs = rsqrtf(q * (1.0f / 128.0f) + 1e-5f);

    float4 gg = __ldg((const float4*)(g + lane * 4));
    float4 bb = __ldg((const float4*)(b + lane * 4));
    float4 o4;
    o4.x = fmaxf(fmaf(d0 * rs, gg.x, bb.x), 0.f);
    o4.y = fmaxf(fmaf(d1 * rs, gg.y, bb.y), 0.f);
    o4.z = fmaxf(fmaf(d2 * rs, gg.z, bb.z), 0.f);
    o4.w = fmaxf(fmaf(d3 * rs, gg.w, bb.w), 0.f);
    *(float4*)(g_h0 + (size_t)warp * IN_C + lane * 4) = o4;     // gemm self path
    st_half4(g_h0h + (size_t)warp * IN_C + lane * 4, o4);       // scatter path
}

// ---------------- edge scatter-add (fp16 gather, fp32 atomics) -------------
// 8 edges per warp: 8 independent 8B fp16 gathers + 8 red.v4.f32 in flight.
__global__ void scatter_edges(const __half* __restrict__ h, const int* __restrict__ src,
                              const int* __restrict__ dst, float* __restrict__ agg,
                              int* __restrict__ cnt, int E) {
    int warp = (blockIdx.x * blockDim.x + threadIdx.x) >> 5;
    int lane = threadIdx.x & 31;
    int e0 = warp * 8;
    if (e0 >= E) return;

    if (e0 + 8 <= E) {
        int4 sa = __ldg((const int4*)(src + e0));
        int4 sb = __ldg((const int4*)(src + e0 + 4));
        int4 da = __ldg((const int4*)(dst + e0));
        int4 db = __ldg((const int4*)(dst + e0 + 4));
        int s[8] = {sa.x, sa.y, sa.z, sa.w, sb.x, sb.y, sb.z, sb.w};
        int d[8] = {da.x, da.y, da.z, da.w, db.x, db.y, db.z, db.w};
        float4 v[8];
#pragma unroll
        for (int j = 0; j < 8; ++j)
            v[j] = ld_half4(h + (size_t)s[j] * IN_C + lane * 4);
#pragma unroll
        for (int j = 0; j < 8; ++j) {
            float* p = agg + (size_t)d[j] * IN_C + lane * 4;
            asm volatile("red.global.add.v4.f32 [%0], {%1,%2,%3,%4};"
                         :: "l"(p), "f"(v[j].x), "f"(v[j].y), "f"(v[j].z), "f"(v[j].w)
                         : "memory");
        }
        if (lane < 8) {
            int dd = (lane == 0) ? da.x : (lane == 1) ? da.y : (lane == 2) ? da.z :
                     (lane == 3) ? da.w : (lane == 4) ? db.x : (lane == 5) ? db.y :
                     (lane == 6) ? db.z : db.w;
            asm volatile("red.global.add.u32 [%0], %1;" :: "l"(cnt + dd), "r"(1) : "memory");
        }
    } else {
        for (int e = e0; e < E; ++e) {
            int s = __ldg(src + e);
            int d = __ldg(dst + e);
            float4 v = ld_half4(h + (size_t)s * IN_C + lane * 4);
            float* p = agg + (size_t)d * IN_C + lane * 4;
            asm volatile("red.global.add.v4.f32 [%0], {%1,%2,%3,%4};"
                         :: "l"(p), "f"(v.x), "f"(v.y), "f"(v.z), "f"(v.w)
                         : "memory");
            if (lane == 0)
                asm volatile("red.global.add.u32 [%0], %1;" :: "l"(cnt + d), "r"(1) : "memory");
        }
    }
}

// ---------------- tensor-core fused SAGE GEMM -------------------------------
// out[n,128] = (agg*rinv)[n,128] @ Wl^T + bias + self[n,128] @ Wr^T (+relu)
// 128 threads = 4 warps (2M x 2N); CTA tile (MFRAG*32) x 128; K chunks 32,
// cp.async double-buffered; mma.sync m16n8k8 tf32, fp32 accumulate.
// Optionally also emits fp16 copy of the output (for the next scatter).
template<int MFRAG, int DO_RELU, int WRITE_HALF>
__global__ __launch_bounds__(128)
void sage_gemm_tc(const float* __restrict__ agg, const int* __restrict__ cnt,
                  const float* __restrict__ selfh, const float* __restrict__ Wt,
                  const float* __restrict__ bias, float* __restrict__ out,
                  __half* __restrict__ outh, int n) {
    constexpr int TM = MFRAG * 32;

    __shared__ float As[2][TM][36];    // banks: 4g+tig -> conflict-free frag loads
    __shared__ float Ws[2][32][136];   // banks: 8tig+g -> conflict-free frag loads
    __shared__ float rinv_s[TM];

    int tid  = threadIdx.x;
    int lane = tid & 31;
    int w    = tid >> 5;
    int g    = lane >> 2;      // groupID 0..7
    int tig  = lane & 3;       // thread-in-group 0..3
    int wm   = w >> 1;         // M split
    int wn   = w & 1;          // N split
    int row0 = blockIdx.x * TM;

    if (tid < TM) {
        int r = row0 + tid;
        rinv_s[tid] = (r < n) ? (1.0f / fmaxf((float)__ldg(cnt + r), 1.0f)) : 0.0f;
    }
    __syncthreads();

    float rv[MFRAG][2];
#pragma unroll
    for (int mf = 0; mf < MFRAG; ++mf) {
        int rl = wm * MFRAG * 16 + mf * 16 + g;
        rv[mf][0] = rinv_s[rl];
        rv[mf][1] = rinv_s[rl + 8];
    }

    auto copyA = [&](int c, int buf) {
        const float* base = (c < 4) ? agg : selfh;
        int kOff = (c & 3) * 32;
#pragma unroll
        for (int i = 0; i < TM / 16; ++i) {
            int idx = tid + i * 128;
            int r = idx >> 3, seg = idx & 7;
            const float* src = base + (size_t)(row0 + r) * 128 + kOff + seg * 4;
            cp16((unsigned)__cvta_generic_to_shared(&As[buf][r][seg * 4]),
                 src, (row0 + r) < n);
        }
    };
    auto copyW = [&](int c, int buf) {
#pragma unroll
        for (int i = 0; i < 8; ++i) {
            int idx = tid + i * 128;
            int r = idx >> 5, seg = idx & 31;
            const float* src = Wt + (size_t)(c * 32 + r) * 128 + seg * 4;
            cp16((unsigned)__cvta_generic_to_shared(&Ws[buf][r][seg * 4]),
                 src, true);
        }
    };

    float acc[MFRAG][8][4];
#pragma unroll
    for (int mf = 0; mf < MFRAG; ++mf)
#pragma unroll
        for (int nt = 0; nt < 8; ++nt)
#pragma unroll
            for (int q = 0; q < 4; ++q) acc[mf][nt][q] = 0.f;

    copyA(0, 0); copyW(0, 0); cp_commit();

#pragma unroll
    for (int c = 0; c < 8; ++c) {
        int buf = c & 1;
        cp_wait0();
        __syncthreads();                       // chunk c visible; buf^1 reads done
        if (c < 7) { copyA(c + 1, buf ^ 1); copyW(c + 1, buf ^ 1); cp_commit(); }

        float s0[MFRAG], s1[MFRAG];
#pragma unroll
        for (int mf = 0; mf < MFRAG; ++mf) {
            s0[mf] = (c < 4) ? rv[mf][0] : 1.0f;
            s1[mf] = (c < 4) ? rv[mf][1] : 1.0f;
        }

#pragma unroll
        for (int ks = 0; ks < 4; ++ks) {
            int kk = ks * 8;
            unsigned a[MFRAG][4];
#pragma unroll
            for (int mf = 0; mf < MFRAG; ++mf) {
                int r0 = wm * MFRAG * 16 + mf * 16 + g;
                a[mf][0] = cvt_tf32(As[buf][r0][kk + tig]         * s0[mf]);
                a[mf][1] = cvt_tf32(As[buf][r0 + 8][kk + tig]     * s1[mf]);
                a[mf][2] = cvt_tf32(As[buf][r0][kk + tig + 4]     * s0[mf]);
                a[mf][3] = cvt_tf32(As[buf][r0 + 8][kk + tig + 4] * s1[mf]);
            }
            unsigned b[8][2];
#pragma unroll
            for (int nt = 0; nt < 8; ++nt) {
                int ncol = wn * 64 + nt * 8 + g;
                b[nt][0] = __float_as_uint(Ws[buf][kk + tig][ncol]);      // pre-rounded
                b[nt][1] = __float_as_uint(Ws[buf][kk + tig + 4][ncol]);
            }
#pragma unroll
            for (int mf = 0; mf < MFRAG; ++mf)
#pragma unroll
                for (int nt = 0; nt < 8; ++nt)
                    mma_tf32(acc[mf][nt], a[mf], b[nt]);
        }
    }

    // epilogue: bias (+relu), fp32 (+ optional fp16) stores
#pragma unroll
    for (int mf = 0; mf < MFRAG; ++mf) {
        int rbase = row0 + wm * MFRAG * 16 + mf * 16 + g;
#pragma unroll
        for (int nt = 0; nt < 8; ++nt) {
            int cl = wn * 64 + nt * 8 + tig * 2;
            float2 bb = __ldg((const float2*)(bias + cl));
            float2 o0, o1;
            o0.x = acc[mf][nt][0] + bb.x;
            o0.y = acc[mf][nt][1] + bb.y;
            o1.x = acc[mf][nt][2] + bb.x;
            o1.y = acc[mf][nt][3] + bb.y;
            if (DO_RELU) {
                o0.x = fmaxf(o0.x, 0.f); o0.y = fmaxf(o0.y, 0.f);
                o1.x = fmaxf(o1.x, 0.f); o1.y = fmaxf(o1.y, 0.f);
            }
            if (rbase < n) {
                *(float2*)(out + (size_t)rbase * 128 + cl) = o0;
                if (WRITE_HALF) {
                    __half2 hh = __floats2half2_rn(o0.x, o0.y);
                    *(__half2*)(outh + (size_t)rbase * 128 + cl) = hh;
                }
            }
            if (rbase + 8 < n) {
                *(float2*)(out + (size_t)(rbase + 8) * 128 + cl) = o1;
                if (WRITE_HALF) {
                    __half2 hh = __floats2half2_rn(o1.x, o1.y);
                    *(__half2*)(outh + (size_t)(rbase + 8) * 128 + cl) = hh;
                }
            }
        }
    }
}

// ---------------- host launcher --------------------------------------------
extern "C" void kernel_launch(void* const* d_in, const int* in_sizes, int n_in,
                              void* d_out, int out_size) {
    int ix = 0, is1 = 1, id1 = 2, is2 = 3, id2 = 4;
    int iemb, ig, ib, iwl1, ibl1, iwr1, iwl2, ibl2, iwr2;
    if (n_in >= 16) {
        iemb = 7; ig = 8; ib = 9; iwl1 = 10; ibl1 = 11; iwr1 = 12;
        iwl2 = 13; ibl2 = 14; iwr2 = 15;
    } else {
        iemb = 5; ig = 6; ib = 7; iwl1 = 8; ibl1 = 9; iwr1 = 10;
        iwl2 = 11; ibl2 = 12; iwr2 = 13;
    }

    const int*   x    = (const int*)d_in[ix];
    const int*   src1 = (const int*)d_in[is1];
    const int*   dst1 = (const int*)d_in[id1];
    const int*   src2 = (const int*)d_in[is2];
    const int*   dst2 = (const int*)d_in[id2];
    const float* emb  = (const float*)d_in[iemb];
    const float* ln_g = (const float*)d_in[ig];
    const float* ln_b = (const float*)d_in[ib];
    const float* Wl1  = (const float*)d_in[iwl1];
    const float* bl1  = (const float*)d_in[ibl1];
    const float* Wr1  = (const float*)d_in[iwr1];
    const float* Wl2  = (const float*)d_in[iwl2];
    const float* bl2  = (const float*)d_in[ibl2];
    const float* Wr2  = (const float*)d_in[iwr2];

    int N0 = in_sizes[ix] / W_BAG;
    int E1 = in_sizes[is1];
    int E2 = in_sizes[is2];

    float *h0, *h1, *agg1, *agg2, *wt1, *wt2;
    __half *h0h, *h1h;
    int *cnt1, *cnt2;
    cudaGetSymbolAddress((void**)&h0,   g_h0);
    cudaGetSymbolAddress((void**)&h0h,  g_h0h);
    cudaGetSymbolAddress((void**)&h1,   g_h1);
    cudaGetSymbolAddress((void**)&h1h,  g_h1h);
    cudaGetSymbolAddress((void**)&agg1, g_agg1);
    cudaGetSymbolAddress((void**)&agg2, g_agg2);
    cudaGetSymbolAddress((void**)&cnt1, g_cnt1);
    cudaGetSymbolAddress((void**)&cnt2, g_cnt2);
    cudaGetSymbolAddress((void**)&wt1,  g_Wt1);
    cudaGetSymbolAddress((void**)&wt2,  g_Wt2);

    // 1. zero accumulators + tf32 weight prep + fp16 emb conversion
    init_scratch<<<1024, 256>>>(Wl1, Wr1, Wl2, Wr2, emb);

    // 2. embedding bag (fp16 gather) + LN + relu -> h0 (fp32 + fp16)
    embed_ln_relu<<<(N0 * 32 + 255) / 256, 256>>>(x, ln_g, ln_b, N0);

    // 3. layer-1 aggregation (fp16 gather, 8 edges/warp)
    scatter_edges<<<(E1 + 63) / 64, 256>>>(h0h, src1, dst1, agg1, cnt1, E1);

    // 4. layer-1 tensor-core GEMM + relu -> h1 (fp32 + fp16)
    sage_gemm_tc<2, 1, 1><<<(N1_C + 63) / 64, 128>>>(agg1, cnt1, h0, wt1, bl1,
                                                     h1, h1h, N1_C);

    // 5. layer-2 aggregation (fp16 gather)
    scatter_edges<<<(E2 + 63) / 64, 256>>>(h1h, src2, dst2, agg2, cnt2, E2);

    // 6. layer-2 tensor-core GEMM -> d_out (fp32 only)
    sage_gemm_tc<1, 0, 0><<<(N2_C + 31) / 32, 128>>>(agg2, cnt2, h1, wt2, bl2,
                                                     (float*)d_out, nullptr, N2_C);
}

// round 10
// speedup vs baseline: 2.0199x; 1.0133x over previous
#include <cuda_runtime.h>
#include <cuda_fp16.h>
#include <cstdint>

// ---------------- problem constants (fixed by the dataset) ----------------
#define IN_C   128
#define LEAF   50000
#define N0_MAX 100000
#define W_BAG  16
#define N1_C   25000
#define N2_C   5000
#define E1_MAX 500000
#define E2_MAX 100000

// ---------------- device scratch (allocation-free rule) -------------------
__device__ __half g_embh[(size_t)LEAF * IN_C];    // 12.8 MB fp16 emb table
__device__ __half g_h0h[(size_t)N0_MAX * IN_C];   // 25.6 MB fp16 h0
__device__ __half g_h1h[(size_t)N1_C * IN_C];     //  6.4 MB fp16 h1
__device__ float  g_A1[(size_t)N1_C * 256];       // 25.6 MB [mean|self] layer1
__device__ float  g_A2[(size_t)N2_C * 256];       //  5.1 MB [mean|self] layer2
__device__ int    g_off1[N1_C + 1];
__device__ int    g_off2[N2_C + 1];
__device__ int    g_cur1[N1_C];
__device__ int    g_cur2[N2_C];
__device__ int    g_adj1[E1_MAX];
__device__ int    g_adj2[E2_MAX];
__device__ float  g_Wt1[256 * 128];               // [k][t] combined (Wl|Wr), tf32-rounded
__device__ float  g_Wt2[256 * 128];

// ---------------- small asm helpers ----------------------------------------
__device__ __forceinline__ unsigned cvt_tf32(float x) {
    unsigned u;
    asm("cvt.rna.tf32.f32 %0, %1;" : "=r"(u) : "f"(x));
    return u;
}
__device__ __forceinline__ void mma_tf32(float* d, const unsigned* a, const unsigned* b) {
    asm volatile(
        "mma.sync.aligned.m16n8k8.row.col.f32.tf32.tf32.f32 "
        "{%0,%1,%2,%3}, {%4,%5,%6,%7}, {%8,%9}, {%0,%1,%2,%3};"
        : "+f"(d[0]), "+f"(d[1]), "+f"(d[2]), "+f"(d[3])
        : "r"(a[0]), "r"(a[1]), "r"(a[2]), "r"(a[3]), "r"(b[0]), "r"(b[1]));
}
__device__ __forceinline__ void cp16(unsigned smem_dst, const void* gsrc, bool pred) {
    int sz = pred ? 16 : 0;
    asm volatile("cp.async.cg.shared.global [%0], [%1], 16, %2;"
                 :: "r"(smem_dst), "l"(gsrc), "r"(sz));
}
__device__ __forceinline__ void cp_commit() {
    asm volatile("cp.async.commit_group;");
}
__device__ __forceinline__ void cp_wait0() {
    asm volatile("cp.async.wait_group 0;");
}

// 4 halves -> float4 (8B load)
__device__ __forceinline__ float4 ld_half4(const __half* p) {
    uint2 r = __ldg((const uint2*)p);
    __half2 a = *reinterpret_cast<__half2*>(&r.x);
    __half2 b = *reinterpret_cast<__half2*>(&r.y);
    float2 fa = __half22float2(a), fb = __half22float2(b);
    return make_float4(fa.x, fa.y, fb.x, fb.y);
}
// float4 -> 4 halves (8B store)
__device__ __forceinline__ void st_half4(__half* p, float4 v) {
    __half2 a = __floats2half2_rn(v.x, v.y);
    __half2 b = __floats2half2_rn(v.z, v.w);
    uint2 r;
    r.x = *reinterpret_cast<unsigned*>(&a);
    r.y = *reinterpret_cast<unsigned*>(&b);
    *(uint2*)p = r;
}

// ---------------- init: zero CSR heads + weight prep + emb fp16 ------------
__global__ void init_scratch(const float* __restrict__ Wl1, const float* __restrict__ Wr1,
                             const float* __restrict__ Wl2, const float* __restrict__ Wr2,
                             const float* __restrict__ emb) {
    int i  = blockIdx.x * blockDim.x + threadIdx.x;
    int st = gridDim.x * blockDim.x;
    for (int j = i; j <= N1_C; j += st) g_off1[j] = 0;
    for (int j = i; j <= N2_C; j += st) g_off2[j] = 0;
    for (int j = i; j < 256 * 128; j += st) {
        int k = j >> 7;
        int t = j & 127;
        float w1 = (k < 128) ? Wl1[t * 128 + k] : Wr1[t * 128 + (k - 128)];
        float w2 = (k < 128) ? Wl2[t * 128 + k] : Wr2[t * 128 + (k - 128)];
        g_Wt1[j] = __uint_as_float(cvt_tf32(w1));   // pre-rounded to tf32
        g_Wt2[j] = __uint_as_float(cvt_tf32(w2));
    }
    // emb fp32 -> fp16
    for (int j = i; j < LEAF * IN_C / 4; j += st) {
        float4 v = __ldg((const float4*)(emb + (size_t)j * 4));
        st_half4(g_embh + (size_t)j * 4, v);
    }
}

// ---------------- CSR build: histogram (both layers, one launch) -----------
__global__ void hist_edges(const int* __restrict__ dst1, int E1,
                           const int* __restrict__ dst2, int E2) {
    int i = blockIdx.x * blockDim.x + threadIdx.x;
    if (i < E1) {
        atomicAdd(&g_off1[__ldg(dst1 + i) + 1], 1);
    } else if (i < E1 + E2) {
        atomicAdd(&g_off2[__ldg(dst2 + (i - E1)) + 1], 1);
    }
}

// ---------------- CSR build: prefix scan (one CTA per layer) ---------------
__global__ __launch_bounds__(1024)
void scan_offsets() {
    int* off = blockIdx.x ? g_off2 : g_off1;
    int* cur = blockIdx.x ? g_cur2 : g_cur1;
    int  n   = blockIdx.x ? N2_C : N1_C;
    __shared__ int sm[1024];

    int t = threadIdx.x;
    int C = (n + 1023) / 1024;
    int lo = t * C;
    int hi = min(n, lo + C);

    int s = 0;
    for (int i = lo; i < hi; ++i) s += off[1 + i];
    sm[t] = s;
    __syncthreads();
    // Hillis-Steele inclusive scan over 1024 partials
#pragma unroll
    for (int ofs = 1; ofs < 1024; ofs <<= 1) {
        int v = (t >= ofs) ? sm[t - ofs] : 0;
        __syncthreads();
        sm[t] += v;
        __syncthreads();
    }
    int run = sm[t] - s;   // exclusive prefix of this thread's chunk
    for (int i = lo; i < hi; ++i) {
        run += off[1 + i];
        off[1 + i] = run;
    }
    __syncthreads();
    // cursors start at row begin (off[0] == 0 from init)
    for (int i = t; i < n; i += 1024) cur[i] = off[i];
}

// ---------------- CSR build: fill adjacency (both layers) ------------------
__global__ void fill_edges(const int* __restrict__ src1, const int* __restrict__ dst1, int E1,
                           const int* __restrict__ src2, const int* __restrict__ dst2, int E2) {
    int i = blockIdx.x * blockDim.x + threadIdx.x;
    if (i < E1) {
        int d = __ldg(dst1 + i);
        int pos = atomicAdd(&g_cur1[d], 1);
        g_adj1[pos] = __ldg(src1 + i);
    } else if (i < E1 + E2) {
        int e = i - E1;
        int d = __ldg(dst2 + e);
        int pos = atomicAdd(&g_cur2[d], 1);
        g_adj2[pos] = __ldg(src2 + e);
    }
}

// ---------------- embedding bag sum + layernorm + relu (fp16 in/out) -------
__global__ void embed_ln_relu(const int* __restrict__ x, const float* __restrict__ g,
                              const float* __restrict__ b, int N0) {
    int warp = (blockIdx.x * blockDim.x + threadIdx.x) >> 5;
    int lane = threadIdx.x & 31;
    if (warp >= N0) return;

    int idx_l = (lane < W_BAG) ? __ldg(x + (size_t)warp * W_BAG + lane) : 0;

    float4 a0 = make_float4(0.f, 0.f, 0.f, 0.f);
    float4 a1 = make_float4(0.f, 0.f, 0.f, 0.f);
#pragma unroll
    for (int w = 0; w < W_BAG; w += 2) {
        int i0 = __shfl_sync(0xffffffffu, idx_l, w);
        int i1 = __shfl_sync(0xffffffffu, idx_l, w + 1);
        float4 e0 = ld_half4(g_embh + (size_t)i0 * IN_C + lane * 4);
        float4 e1 = ld_half4(g_embh + (size_t)i1 * IN_C + lane * 4);
        a0.x += e0.x; a0.y += e0.y; a0.z += e0.z; a0.w += e0.w;
        a1.x += e1.x; a1.y += e1.y; a1.z += e1.z; a1.w += e1.w;
    }
    float4 acc;
    acc.x = a0.x + a1.x; acc.y = a0.y + a1.y;
    acc.z = a0.z + a1.z; acc.w = a0.w + a1.w;

    float s = acc.x + acc.y + acc.z + acc.w;
#pragma unroll
    for (int o = 16; o; o >>= 1) s += __shfl_xor_sync(0xffffffffu, s, o);
    float mu = s * (1.0f / 128.0f);
    float d0 = acc.x - mu, d1 = acc.y - mu, d2 = acc.z - mu, d3 = acc.w - mu;
    float q = d0 * d0 + d1 * d1 + d2 * d2 + d3 * d3;
#pragma unroll
    for (int o = 16; o; o >>= 1) q += __shfl_xor_sync(0xffffffffu, q, o);
    float rs = rsqrtf(q * (1.0f / 128.0f) + 1e-5f);

    float4 gg = __ldg((const float4*)(g + lane * 4));
    float4 bb = __ldg((const float4*)(b + lane * 4));
    float4 o4;
    o4.x = fmaxf(fmaf(d0 * rs, gg.x, bb.x), 0.f);
    o4.y = fmaxf(fmaf(d1 * rs, gg.y, bb.y), 0.f);
    o4.z = fmaxf(fmaf(d2 * rs, gg.z, bb.z), 0.f);
    o4.w = fmaxf(fmaf(d3 * rs, gg.w, bb.w), 0.f);
    st_half4(g_h0h + (size_t)warp * IN_C + lane * 4, o4);
}

// ---------------- pull aggregation: A[r] = [mean_{src in adj(r)} h | h[r]] --
// one warp per target row; lane owns channels 4l..4l+3; 4-edge unroll.
__global__ void pull_mean(const __half* __restrict__ h, const int* __restrict__ off,
                          const int* __restrict__ adj, float* __restrict__ A, int n) {
    int warp = (blockIdx.x * blockDim.x + threadIdx.x) >> 5;
    int lane = threadIdx.x & 31;
    if (warp >= n) return;

    int o0 = __ldg(off + warp);
    int o1 = __ldg(off + warp + 1);

    float4 acc0 = make_float4(0.f, 0.f, 0.f, 0.f);
    float4 acc1 = make_float4(0.f, 0.f, 0.f, 0.f);
    int d = o0;
    for (; d + 4 <= o1; d += 4) {
        int s0 = __ldg(adj + d);
        int s1 = __ldg(adj + d + 1);
        int s2 = __ldg(adj + d + 2);
        int s3 = __ldg(adj + d + 3);
        float4 e0 = ld_half4(h + (size_t)s0 * IN_C + lane * 4);
        float4 e1 = ld_half4(h + (size_t)s1 * IN_C + lane * 4);
        float4 e2 = ld_half4(h + (size_t)s2 * IN_C + lane * 4);
        float4 e3 = ld_half4(h + (size_t)s3 * IN_C + lane * 4);
        acc0.x += e0.x + e2.x; acc0.y += e0.y + e2.y;
        acc0.z += e0.z + e2.z; acc0.w += e0.w + e2.w;
        acc1.x += e1.x + e3.x; acc1.y += e1.y + e3.y;
        acc1.z += e1.z + e3.z; acc1.w += e1.w + e3.w;
    }
    for (; d < o1; ++d) {
        int s = __ldg(adj + d);
        float4 e = ld_half4(h + (size_t)s * IN_C + lane * 4);
        acc0.x += e.x; acc0.y += e.y; acc0.z += e.z; acc0.w += e.w;
    }
    float inv = (o1 > o0) ? (1.0f / (float)(o1 - o0)) : 0.0f;
    float4 m;
    m.x = (acc0.x + acc1.x) * inv;
    m.y = (acc0.y + acc1.y) * inv;
    m.z = (acc0.z + acc1.z) * inv;
    m.w = (acc0.w + acc1.w) * inv;
    *(float4*)(A + (size_t)warp * 256 + lane * 4) = m;

    float4 sv = ld_half4(h + (size_t)warp * IN_C + lane * 4);
    *(float4*)(A + (size_t)warp * 256 + 128 + lane * 4) = sv;
}

// ---------------- tensor-core fused SAGE GEMM -------------------------------
// out[n,128] = A[n,0:128] @ Wl^T + bias + A[n,128:256] @ Wr^T (+relu)
// A is the contiguous [mean|self] matrix. 128 threads = 4 warps (2M x 2N);
// CTA tile (MFRAG*32) x 128; K chunks 32, cp.async double-buffered;
// mma.sync m16n8k8 tf32, fp32 accumulate.
template<int MFRAG, int DO_RELU, int WRITE_F32, int WRITE_HALF>
__global__ __launch_bounds__(128)
void sage_gemm_tc(const float* __restrict__ A, const float* __restrict__ Wt,
                  const float* __restrict__ bias, float* __restrict__ out,
                  __half* __restrict__ outh, int n) {
    constexpr int TM = MFRAG * 32;

    __shared__ float As[2][TM][36];    // banks: 4g+tig -> conflict-free frag loads
    __shared__ float Ws[2][32][136];   // banks: 8tig+g -> conflict-free frag loads

    int tid  = threadIdx.x;
    int lane = tid & 31;
    int w    = tid >> 5;
    int g    = lane >> 2;      // groupID 0..7
    int tig  = lane & 3;       // thread-in-group 0..3
    int wm   = w >> 1;         // M split
    int wn   = w & 1;          // N split
    int row0 = blockIdx.x * TM;

    auto copyA = [&](int c, int buf) {
#pragma unroll
        for (int i = 0; i < TM / 16; ++i) {
            int idx = tid + i * 128;
            int r = idx >> 3, seg = idx & 7;
            const float* src = A + (size_t)(row0 + r) * 256 + c * 32 + seg * 4;
            cp16((unsigned)__cvta_generic_to_shared(&As[buf][r][seg * 4]),
                 src, (row0 + r) < n);
        }
    };
    auto copyW = [&](int c, int buf) {
#pragma unroll
        for (int i = 0; i < 8; ++i) {
            int idx = tid + i * 128;
            int r = idx >> 5, seg = idx & 31;
            const float* src = Wt + (size_t)(c * 32 + r) * 128 + seg * 4;
            cp16((unsigned)__cvta_generic_to_shared(&Ws[buf][r][seg * 4]),
                 src, true);
        }
    };

    float acc[MFRAG][8][4];
#pragma unroll
    for (int mf = 0; mf < MFRAG; ++mf)
#pragma unroll
        for (int nt = 0; nt < 8; ++nt)
#pragma unroll
            for (int q = 0; q < 4; ++q) acc[mf][nt][q] = 0.f;

    copyA(0, 0); copyW(0, 0); cp_commit();

#pragma unroll
    for (int c = 0; c < 8; ++c) {
        int buf = c & 1;
        cp_wait0();
        __syncthreads();                       // chunk c visible; buf^1 reads done
        if (c < 7) { copyA(c + 1, buf ^ 1); copyW(c + 1, buf ^ 1); cp_commit(); }

#pragma unroll
        for (int ks = 0; ks < 4; ++ks) {
            int kk = ks * 8;
            unsigned a[MFRAG][4];
#pragma unroll
            for (int mf = 0; mf < MFRAG; ++mf) {
                int r0 = wm * MFRAG * 16 + mf * 16 + g;
                a[mf][0] = cvt_tf32(As[buf][r0][kk + tig]);
                a[mf][1] = cvt_tf32(As[buf][r0 + 8][kk + tig]);
                a[mf][2] = cvt_tf32(As[buf][r0][kk + tig + 4]);
                a[mf][3] = cvt_tf32(As[buf][r0 + 8][kk + tig + 4]);
            }
            unsigned b[8][2];
#pragma unroll
            for (int nt = 0; nt < 8; ++nt) {
                int ncol = wn * 64 + nt * 8 + g;
                b[nt][0] = __float_as_uint(Ws[buf][kk + tig][ncol]);      // pre-rounded
                b[nt][1] = __float_as_uint(Ws[buf][kk + tig + 4][ncol]);
            }
#pragma unroll
            for (int mf = 0; mf < MFRAG; ++mf)
#pragma unroll
                for (int nt = 0; nt < 8; ++nt)
                    mma_tf32(acc[mf][nt], a[mf], b[nt]);
        }
    }

    // epilogue: bias (+relu), fp32 and/or fp16 stores
#pragma unroll
    for (int mf = 0; mf < MFRAG; ++mf) {
        int rbase = row0 + wm * MFRAG * 16 + mf * 16 + g;
#pragma unroll
        for (int nt = 0; nt < 8; ++nt) {
            int cl = wn * 64 + nt * 8 + tig * 2;
            float2 bb = __ldg((const float2*)(bias + cl));
            float2 o0, o1;
            o0.x = acc[mf][nt][0] + bb.x;
            o0.y = acc[mf][nt][1] + bb.y;
            o1.x = acc[mf][nt][2] + bb.x;
            o1.y = acc[mf][nt][3] + bb.y;
            if (DO_RELU) {
                o0.x = fmaxf(o0.x, 0.f); o0.y = fmaxf(o0.y, 0.f);
                o1.x = fmaxf(o1.x, 0.f); o1.y = fmaxf(o1.y, 0.f);
            }
            if (rbase < n) {
                if (WRITE_F32)
                    *(float2*)(out + (size_t)rbase * 128 + cl) = o0;
                if (WRITE_HALF)
                    *(__half2*)(outh + (size_t)rbase * 128 + cl) =
                        __floats2half2_rn(o0.x, o0.y);
            }
            if (rbase + 8 < n) {
                if (WRITE_F32)
                    *(float2*)(out + (size_t)(rbase + 8) * 128 + cl) = o1;
                if (WRITE_HALF)
                    *(__half2*)(outh + (size_t)(rbase + 8) * 128 + cl) =
                        __floats2half2_rn(o1.x, o1.y);
            }
        }
    }
}

// ---------------- host launcher --------------------------------------------
extern "C" void kernel_launch(void* const* d_in, const int* in_sizes, int n_in,
                              void* d_out, int out_size) {
    int ix = 0, is1 = 1, id1 = 2, is2 = 3, id2 = 4;
    int iemb, ig, ib, iwl1, ibl1, iwr1, iwl2, ibl2, iwr2;
    if (n_in >= 16) {
        iemb = 7; ig = 8; ib = 9; iwl1 = 10; ibl1 = 11; iwr1 = 12;
        iwl2 = 13; ibl2 = 14; iwr2 = 15;
    } else {
        iemb = 5; ig = 6; ib = 7; iwl1 = 8; ibl1 = 9; iwr1 = 10;
        iwl2 = 11; ibl2 = 12; iwr2 = 13;
    }

    const int*   x    = (const int*)d_in[ix];
    const int*   src1 = (const int*)d_in[is1];
    const int*   dst1 = (const int*)d_in[id1];
    const int*   src2 = (const int*)d_in[is2];
    const int*   dst2 = (const int*)d_in[id2];
    const float* emb  = (const float*)d_in[iemb];
    const float* ln_g = (const float*)d_in[ig];
    const float* ln_b = (const float*)d_in[ib];
    const float* Wl1  = (const float*)d_in[iwl1];
    const float* bl1  = (const float*)d_in[ibl1];
    const float* Wr1  = (const float*)d_in[iwr1];
    const float* Wl2  = (const float*)d_in[iwl2];
    const float* bl2  = (const float*)d_in[ibl2];
    const float* Wr2  = (const float*)d_in[iwr2];

    int N0 = in_sizes[ix] / W_BAG;
    int E1 = in_sizes[is1]; if (E1 > E1_MAX) E1 = E1_MAX;
    int E2 = in_sizes[is2]; if (E2 > E2_MAX) E2 = E2_MAX;

    __half *h0h, *h1h;
    float *A1, *A2, *wt1, *wt2;
    int *off1, *off2, *adj1, *adj2;
    cudaGetSymbolAddress((void**)&h0h,  g_h0h);
    cudaGetSymbolAddress((void**)&h1h,  g_h1h);
    cudaGetSymbolAddress((void**)&A1,   g_A1);
    cudaGetSymbolAddress((void**)&A2,   g_A2);
    cudaGetSymbolAddress((void**)&wt1,  g_Wt1);
    cudaGetSymbolAddress((void**)&wt2,  g_Wt2);
    cudaGetSymbolAddress((void**)&off1, g_off1);
    cudaGetSymbolAddress((void**)&off2, g_off2);
    cudaGetSymbolAddress((void**)&adj1, g_adj1);
    cudaGetSymbolAddress((void**)&adj2, g_adj2);

    // 1. zero CSR heads + tf32 weight prep + fp16 emb conversion
    init_scratch<<<1024, 256>>>(Wl1, Wr1, Wl2, Wr2, emb);

    // 2. embedding bag (fp16) + LN + relu -> h0h
    embed_ln_relu<<<(N0 * 32 + 255) / 256, 256>>>(x, ln_g, ln_b, N0);

    // 3. CSR build for BOTH layers (independent of features)
    int Etot = E1 + E2;
    hist_edges<<<(Etot + 255) / 256, 256>>>(dst1, E1, dst2, E2);
    scan_offsets<<<2, 1024>>>();
    fill_edges<<<(Etot + 255) / 256, 256>>>(src1, dst1, E1, src2, dst2, E2);

    // 4. layer-1 pull aggregation -> A1 = [mean | self]
    pull_mean<<<(N1_C * 32 + 255) / 256, 256>>>(h0h, off1, adj1, A1, N1_C);

    // 5. layer-1 tensor-core GEMM + relu -> h1h (fp16 only)
    sage_gemm_tc<2, 1, 0, 1><<<(N1_C + 63) / 64, 128>>>(A1, wt1, bl1,
                                                        nullptr, h1h, N1_C);

    // 6. layer-2 pull aggregation -> A2
    pull_mean<<<(N2_C * 32 + 255) / 256, 256>>>(h1h, off2, adj2, A2, N2_C);

    // 7. layer-2 tensor-core GEMM -> d_out (fp32)
    sage_gemm_tc<1, 0, 1, 0><<<(N2_C + 31) / 32, 128>>>(A2, wt2, bl2,
                                                        (float*)d_out, nullptr, N2_C);
}

// round 11
// speedup vs baseline: 2.4031x; 1.1897x over previous
#include <cuda_runtime.h>
#include <cuda_fp16.h>
#include <cstdint>

// ---------------- problem constants (fixed by the dataset) ----------------
#define IN_C   128
#define LEAF   50000
#define N0_MAX 100000
#define W_BAG  16
#define N1_C   25000
#define N2_C   5000
#define E1_MAX 500000
#define E2_MAX 100000

// ---------------- device scratch (allocation-free rule) -------------------
__device__ __half g_embh[(size_t)LEAF * IN_C];    // 12.8 MB fp16 emb table
__device__ __half g_h0h[(size_t)N0_MAX * IN_C];   // 25.6 MB fp16 h0
__device__ __half g_h1h[(size_t)N1_C * IN_C];     //  6.4 MB fp16 h1
__device__ float  g_A1[(size_t)N1_C * 256];       // 25.6 MB [mean|self] layer1
__device__ float  g_A2[(size_t)N2_C * 256];       //  5.1 MB [mean|self] layer2
__device__ int    g_off1[N1_C + 1];
__device__ int    g_off2[N2_C + 1];
__device__ int    g_cur1[N1_C];
__device__ int    g_cur2[N2_C];
__device__ int    g_adj1[E1_MAX];
__device__ int    g_adj2[E2_MAX];
__device__ float  g_Wt1[256 * 128];               // [k][t] combined (Wl|Wr), tf32-rounded
__device__ float  g_Wt2[256 * 128];

// ---------------- small asm helpers ----------------------------------------
__device__ __forceinline__ unsigned cvt_tf32(float x) {
    unsigned u;
    asm("cvt.rna.tf32.f32 %0, %1;" : "=r"(u) : "f"(x));
    return u;
}
__device__ __forceinline__ void mma_tf32(float* d, const unsigned* a, const unsigned* b) {
    asm volatile(
        "mma.sync.aligned.m16n8k8.row.col.f32.tf32.tf32.f32 "
        "{%0,%1,%2,%3}, {%4,%5,%6,%7}, {%8,%9}, {%0,%1,%2,%3};"
        : "+f"(d[0]), "+f"(d[1]), "+f"(d[2]), "+f"(d[3])
        : "r"(a[0]), "r"(a[1]), "r"(a[2]), "r"(a[3]), "r"(b[0]), "r"(b[1]));
}
__device__ __forceinline__ void cp16(unsigned smem_dst, const void* gsrc, bool pred) {
    int sz = pred ? 16 : 0;
    asm volatile("cp.async.cg.shared.global [%0], [%1], 16, %2;"
                 :: "r"(smem_dst), "l"(gsrc), "r"(sz));
}
__device__ __forceinline__ void cp_commit() {
    asm volatile("cp.async.commit_group;");
}
__device__ __forceinline__ void cp_wait0() {
    asm volatile("cp.async.wait_group 0;");
}

// 4 halves -> float4 (8B load)
__device__ __forceinline__ float4 ld_half4(const __half* p) {
    uint2 r = __ldg((const uint2*)p);
    __half2 a = *reinterpret_cast<__half2*>(&r.x);
    __half2 b = *reinterpret_cast<__half2*>(&r.y);
    float2 fa = __half22float2(a), fb = __half22float2(b);
    return make_float4(fa.x, fa.y, fb.x, fb.y);
}
// float4 -> 4 halves (8B store)
__device__ __forceinline__ void st_half4(__half* p, float4 v) {
    __half2 a = __floats2half2_rn(v.x, v.y);
    __half2 b = __floats2half2_rn(v.z, v.w);
    uint2 r;
    r.x = *reinterpret_cast<unsigned*>(&a);
    r.y = *reinterpret_cast<unsigned*>(&b);
    *(uint2*)p = r;
}

// ---------------- main-stream init: weight prep + emb fp16 -----------------
__global__ void init_wemb(const float* __restrict__ Wl1, const float* __restrict__ Wr1,
                          const float* __restrict__ Wl2, const float* __restrict__ Wr2,
                          const float* __restrict__ emb) {
    int i  = blockIdx.x * blockDim.x + threadIdx.x;
    int st = gridDim.x * blockDim.x;
    for (int j = i; j < 256 * 128; j += st) {
        int k = j >> 7;
        int t = j & 127;
        float w1 = (k < 128) ? Wl1[t * 128 + k] : Wr1[t * 128 + (k - 128)];
        float w2 = (k < 128) ? Wl2[t * 128 + k] : Wr2[t * 128 + (k - 128)];
        g_Wt1[j] = __uint_as_float(cvt_tf32(w1));   // pre-rounded to tf32
        g_Wt2[j] = __uint_as_float(cvt_tf32(w2));
    }
    for (int j = i; j < LEAF * IN_C / 4; j += st) {
        float4 v = __ldg((const float4*)(emb + (size_t)j * 4));
        st_half4(g_embh + (size_t)j * 4, v);
    }
}

// ---------------- side stream: zero CSR offsets -----------------------------
__global__ void zero_off() {
    int i = blockIdx.x * blockDim.x + threadIdx.x;
    if (i <= N1_C) g_off1[i] = 0;
    if (i <= N2_C) g_off2[i] = 0;
}

// ---------------- side stream: histogram (both layers) ----------------------
__global__ void hist_edges(const int* __restrict__ dst1, int E1,
                           const int* __restrict__ dst2, int E2) {
    int i = blockIdx.x * blockDim.x + threadIdx.x;
    if (i < E1) {
        atomicAdd(&g_off1[__ldg(dst1 + i) + 1], 1);
    } else if (i < E1 + E2) {
        atomicAdd(&g_off2[__ldg(dst2 + (i - E1)) + 1], 1);
    }
}

// ---------------- side stream: warp-shuffle prefix scan ---------------------
// one CTA (1024 threads) per layer; per-thread register chunk, warp scans,
// 2 barriers total. Also seeds the fill cursors.
#define MAXC 25
__global__ __launch_bounds__(1024)
void scan_offsets() {
    int* off = blockIdx.x ? g_off2 : g_off1;
    int* cur = blockIdx.x ? g_cur2 : g_cur1;
    int  n   = blockIdx.x ? N2_C : N1_C;
    __shared__ int wsum[32];

    int t    = threadIdx.x;
    int lane = t & 31;
    int wid  = t >> 5;
    int C  = (n + 1023) >> 10;          // 25 (layer1) or 5 (layer2)
    int lo = t * C;
    int hi = min(n, lo + C);
    int cnt = hi - lo; if (cnt < 0) cnt = 0;

    int v[MAXC];
#pragma unroll
    for (int j = 0; j < MAXC; ++j)
        if (j < cnt) v[j] = off[1 + lo + j];

    int s = 0;
#pragma unroll
    for (int j = 0; j < MAXC; ++j)
        if (j < cnt) s += v[j];
    int sOrig = s;

    // warp-inclusive scan
#pragma unroll
    for (int o = 1; o < 32; o <<= 1) {
        int u = __shfl_up_sync(0xffffffffu, s, o);
        if (lane >= o) s += u;
    }
    if (lane == 31) wsum[wid] = s;
    __syncthreads();
    if (wid == 0) {
        int w = wsum[lane];
#pragma unroll
        for (int o = 1; o < 32; o <<= 1) {
            int u = __shfl_up_sync(0xffffffffu, w, o);
            if (lane >= o) w += u;
        }
        wsum[lane] = w;                 // inclusive warp totals
    }
    __syncthreads();

    int base = (wid ? wsum[wid - 1] : 0) + (s - sOrig);   // exclusive prefix
    int run = base;
#pragma unroll
    for (int j = 0; j < MAXC; ++j) {
        if (j < cnt) {
            cur[lo + j] = run;          // fill cursor = row start
            run += v[j];
            off[1 + lo + j] = run;
        }
    }
}

// ---------------- side stream: fill adjacency (both layers) -----------------
__global__ void fill_edges(const int* __restrict__ src1, const int* __restrict__ dst1, int E1,
                           const int* __restrict__ src2, const int* __restrict__ dst2, int E2) {
    int i = blockIdx.x * blockDim.x + threadIdx.x;
    if (i < E1) {
        int d = __ldg(dst1 + i);
        int pos = atomicAdd(&g_cur1[d], 1);
        g_adj1[pos] = __ldg(src1 + i);
    } else if (i < E1 + E2) {
        int e = i - E1;
        int d = __ldg(dst2 + e);
        int pos = atomicAdd(&g_cur2[d], 1);
        g_adj2[pos] = __ldg(src2 + e);
    }
}

// ---------------- embedding bag sum + layernorm + relu (fp16 in/out) -------
__global__ void embed_ln_relu(const int* __restrict__ x, const float* __restrict__ g,
                              const float* __restrict__ b, int N0) {
    int warp = (blockIdx.x * blockDim.x + threadIdx.x) >> 5;
    int lane = threadIdx.x & 31;
    if (warp >= N0) return;

    int idx_l = (lane < W_BAG) ? __ldg(x + (size_t)warp * W_BAG + lane) : 0;

    float4 a0 = make_float4(0.f, 0.f, 0.f, 0.f);
    float4 a1 = make_float4(0.f, 0.f, 0.f, 0.f);
#pragma unroll
    for (int w = 0; w < W_BAG; w += 2) {
        int i0 = __shfl_sync(0xffffffffu, idx_l, w);
        int i1 = __shfl_sync(0xffffffffu, idx_l, w + 1);
        float4 e0 = ld_half4(g_embh + (size_t)i0 * IN_C + lane * 4);
        float4 e1 = ld_half4(g_embh + (size_t)i1 * IN_C + lane * 4);
        a0.x += e0.x; a0.y += e0.y; a0.z += e0.z; a0.w += e0.w;
        a1.x += e1.x; a1.y += e1.y; a1.z += e1.z; a1.w += e1.w;
    }
    float4 acc;
    acc.x = a0.x + a1.x; acc.y = a0.y + a1.y;
    acc.z = a0.z + a1.z; acc.w = a0.w + a1.w;

    float s = acc.x + acc.y + acc.z + acc.w;
#pragma unroll
    for (int o = 16; o; o >>= 1) s += __shfl_xor_sync(0xffffffffu, s, o);
    float mu = s * (1.0f / 128.0f);
    float d0 = acc.x - mu, d1 = acc.y - mu, d2 = acc.z - mu, d3 = acc.w - mu;
    float q = d0 * d0 + d1 * d1 + d2 * d2 + d3 * d3;
#pragma unroll
    for (int o = 16; o; o >>= 1) q += __shfl_xor_sync(0xffffffffu, q, o);
    float rs = rsqrtf(q * (1.0f / 128.0f) + 1e-5f);

    float4 gg = __ldg((const float4*)(g + lane * 4));
    float4 bb = __ldg((const float4*)(b + lane * 4));
    float4 o4;
    o4.x = fmaxf(fmaf(d0 * rs, gg.x, bb.x), 0.f);
    o4.y = fmaxf(fmaf(d1 * rs, gg.y, bb.y), 0.f);
    o4.z = fmaxf(fmaf(d2 * rs, gg.z, bb.z), 0.f);
    o4.w = fmaxf(fmaf(d3 * rs, gg.w, bb.w), 0.f);
    st_half4(g_h0h + (size_t)warp * IN_C + lane * 4, o4);
}

// ---------------- pull aggregation: A[r] = [mean_{src in adj(r)} h | h[r]] --
__global__ void pull_mean(const __half* __restrict__ h, const int* __restrict__ off,
                          const int* __restrict__ adj, float* __restrict__ A, int n) {
    int warp = (blockIdx.x * blockDim.x + threadIdx.x) >> 5;
    int lane = threadIdx.x & 31;
    if (warp >= n) return;

    int o0 = __ldg(off + warp);
    int o1 = __ldg(off + warp + 1);

    float4 acc0 = make_float4(0.f, 0.f, 0.f, 0.f);
    float4 acc1 = make_float4(0.f, 0.f, 0.f, 0.f);
    int d = o0;
    for (; d + 4 <= o1; d += 4) {
        int s0 = __ldg(adj + d);
        int s1 = __ldg(adj + d + 1);
        int s2 = __ldg(adj + d + 2);
        int s3 = __ldg(adj + d + 3);
        float4 e0 = ld_half4(h + (size_t)s0 * IN_C + lane * 4);
        float4 e1 = ld_half4(h + (size_t)s1 * IN_C + lane * 4);
        float4 e2 = ld_half4(h + (size_t)s2 * IN_C + lane * 4);
        float4 e3 = ld_half4(h + (size_t)s3 * IN_C + lane * 4);
        acc0.x += e0.x + e2.x; acc0.y += e0.y + e2.y;
        acc0.z += e0.z + e2.z; acc0.w += e0.w + e2.w;
        acc1.x += e1.x + e3.x; acc1.y += e1.y + e3.y;
        acc1.z += e1.z + e3.z; acc1.w += e1.w + e3.w;
    }
    for (; d < o1; ++d) {
        int s = __ldg(adj + d);
        float4 e = ld_half4(h + (size_t)s * IN_C + lane * 4);
        acc0.x += e.x; acc0.y += e.y; acc0.z += e.z; acc0.w += e.w;
    }
    float inv = (o1 > o0) ? (1.0f / (float)(o1 - o0)) : 0.0f;
    float4 m;
    m.x = (acc0.x + acc1.x) * inv;
    m.y = (acc0.y + acc1.y) * inv;
    m.z = (acc0.z + acc1.z) * inv;
    m.w = (acc0.w + acc1.w) * inv;
    *(float4*)(A + (size_t)warp * 256 + lane * 4) = m;

    float4 sv = ld_half4(h + (size_t)warp * IN_C + lane * 4);
    *(float4*)(A + (size_t)warp * 256 + 128 + lane * 4) = sv;
}

// ---------------- tensor-core fused SAGE GEMM -------------------------------
template<int MFRAG, int DO_RELU, int WRITE_F32, int WRITE_HALF>
__global__ __launch_bounds__(128)
void sage_gemm_tc(const float* __restrict__ A, const float* __restrict__ Wt,
                  const float* __restrict__ bias, float* __restrict__ out,
                  __half* __restrict__ outh, int n) {
    constexpr int TM = MFRAG * 32;

    __shared__ float As[2][TM][36];    // banks: 4g+tig -> conflict-free frag loads
    __shared__ float Ws[2][32][136];   // banks: 8tig+g -> conflict-free frag loads

    int tid  = threadIdx.x;
    int lane = tid & 31;
    int w    = tid >> 5;
    int g    = lane >> 2;
    int tig  = lane & 3;
    int wm   = w >> 1;
    int wn   = w & 1;
    int row0 = blockIdx.x * TM;

    auto copyA = [&](int c, int buf) {
#pragma unroll
        for (int i = 0; i < TM / 16; ++i) {
            int idx = tid + i * 128;
            int r = idx >> 3, seg = idx & 7;
            const float* src = A + (size_t)(row0 + r) * 256 + c * 32 + seg * 4;
            cp16((unsigned)__cvta_generic_to_shared(&As[buf][r][seg * 4]),
                 src, (row0 + r) < n);
        }
    };
    auto copyW = [&](int c, int buf) {
#pragma unroll
        for (int i = 0; i < 8; ++i) {
            int idx = tid + i * 128;
            int r = idx >> 5, seg = idx & 31;
            const float* src = Wt + (size_t)(c * 32 + r) * 128 + seg * 4;
            cp16((unsigned)__cvta_generic_to_shared(&Ws[buf][r][seg * 4]),
                 src, true);
        }
    };

    float acc[MFRAG][8][4];
#pragma unroll
    for (int mf = 0; mf < MFRAG; ++mf)
#pragma unroll
        for (int nt = 0; nt < 8; ++nt)
#pragma unroll
            for (int q = 0; q < 4; ++q) acc[mf][nt][q] = 0.f;

    copyA(0, 0); copyW(0, 0); cp_commit();

#pragma unroll
    for (int c = 0; c < 8; ++c) {
        int buf = c & 1;
        cp_wait0();
        __syncthreads();
        if (c < 7) { copyA(c + 1, buf ^ 1); copyW(c + 1, buf ^ 1); cp_commit(); }

#pragma unroll
        for (int ks = 0; ks < 4; ++ks) {
            int kk = ks * 8;
            unsigned a[MFRAG][4];
#pragma unroll
            for (int mf = 0; mf < MFRAG; ++mf) {
                int r0 = wm * MFRAG * 16 + mf * 16 + g;
                a[mf][0] = cvt_tf32(As[buf][r0][kk + tig]);
                a[mf][1] = cvt_tf32(As[buf][r0 + 8][kk + tig]);
                a[mf][2] = cvt_tf32(As[buf][r0][kk + tig + 4]);
                a[mf][3] = cvt_tf32(As[buf][r0 + 8][kk + tig + 4]);
            }
            unsigned b[8][2];
#pragma unroll
            for (int nt = 0; nt < 8; ++nt) {
                int ncol = wn * 64 + nt * 8 + g;
                b[nt][0] = __float_as_uint(Ws[buf][kk + tig][ncol]);
                b[nt][1] = __float_as_uint(Ws[buf][kk + tig + 4][ncol]);
            }
#pragma unroll
            for (int mf = 0; mf < MFRAG; ++mf)
#pragma unroll
                for (int nt = 0; nt < 8; ++nt)
                    mma_tf32(acc[mf][nt], a[mf], b[nt]);
        }
    }

#pragma unroll
    for (int mf = 0; mf < MFRAG; ++mf) {
        int rbase = row0 + wm * MFRAG * 16 + mf * 16 + g;
#pragma unroll
        for (int nt = 0; nt < 8; ++nt) {
            int cl = wn * 64 + nt * 8 + tig * 2;
            float2 bb = __ldg((const float2*)(bias + cl));
            float2 o0, o1;
            o0.x = acc[mf][nt][0] + bb.x;
            o0.y = acc[mf][nt][1] + bb.y;
            o1.x = acc[mf][nt][2] + bb.x;
            o1.y = acc[mf][nt][3] + bb.y;
            if (DO_RELU) {
                o0.x = fmaxf(o0.x, 0.f); o0.y = fmaxf(o0.y, 0.f);
                o1.x = fmaxf(o1.x, 0.f); o1.y = fmaxf(o1.y, 0.f);
            }
            if (rbase < n) {
                if (WRITE_F32)
                    *(float2*)(out + (size_t)rbase * 128 + cl) = o0;
                if (WRITE_HALF)
                    *(__half2*)(outh + (size_t)rbase * 128 + cl) =
                        __floats2half2_rn(o0.x, o0.y);
            }
            if (rbase + 8 < n) {
                if (WRITE_F32)
                    *(float2*)(out + (size_t)(rbase + 8) * 128 + cl) = o1;
                if (WRITE_HALF)
                    *(__half2*)(outh + (size_t)(rbase + 8) * 128 + cl) =
                        __floats2half2_rn(o1.x, o1.y);
            }
        }
    }
}

// ---------------- host launcher --------------------------------------------
extern "C" void kernel_launch(void* const* d_in, const int* in_sizes, int n_in,
                              void* d_out, int out_size) {
    int ix = 0, is1 = 1, id1 = 2, is2 = 3, id2 = 4;
    int iemb, ig, ib, iwl1, ibl1, iwr1, iwl2, ibl2, iwr2;
    if (n_in >= 16) {
        iemb = 7; ig = 8; ib = 9; iwl1 = 10; ibl1 = 11; iwr1 = 12;
        iwl2 = 13; ibl2 = 14; iwr2 = 15;
    } else {
        iemb = 5; ig = 6; ib = 7; iwl1 = 8; ibl1 = 9; iwr1 = 10;
        iwl2 = 11; ibl2 = 12; iwr2 = 13;
    }

    const int*   x    = (const int*)d_in[ix];
    const int*   src1 = (const int*)d_in[is1];
    const int*   dst1 = (const int*)d_in[id1];
    const int*   src2 = (const int*)d_in[is2];
    const int*   dst2 = (const int*)d_in[id2];
    const float* emb  = (const float*)d_in[iemb];
    const float* ln_g = (const float*)d_in[ig];
    const float* ln_b = (const float*)d_in[ib];
    const float* Wl1  = (const float*)d_in[iwl1];
    const float* bl1  = (const float*)d_in[ibl1];
    const float* Wr1  = (const float*)d_in[iwr1];
    const float* Wl2  = (const float*)d_in[iwl2];
    const float* bl2  = (const float*)d_in[ibl2];
    const float* Wr2  = (const float*)d_in[iwr2];

    int N0 = in_sizes[ix] / W_BAG;
    int E1 = in_sizes[is1]; if (E1 > E1_MAX) E1 = E1_MAX;
    int E2 = in_sizes[is2]; if (E2 > E2_MAX) E2 = E2_MAX;

    __half *h0h, *h1h;
    float *A1, *A2, *wt1, *wt2;
    int *off1, *off2, *adj1, *adj2;
    cudaGetSymbolAddress((void**)&h0h,  g_h0h);
    cudaGetSymbolAddress((void**)&h1h,  g_h1h);
    cudaGetSymbolAddress((void**)&A1,   g_A1);
    cudaGetSymbolAddress((void**)&A2,   g_A2);
    cudaGetSymbolAddress((void**)&wt1,  g_Wt1);
    cudaGetSymbolAddress((void**)&wt2,  g_Wt2);
    cudaGetSymbolAddress((void**)&off1, g_off1);
    cudaGetSymbolAddress((void**)&off2, g_off2);
    cudaGetSymbolAddress((void**)&adj1, g_adj1);
    cudaGetSymbolAddress((void**)&adj2, g_adj2);

    // side stream + fork/join events (created per call; handles only, no
    // device allocation; ~3 calls total so no meaningful leak)
    cudaStream_t side;
    cudaStreamCreateWithFlags(&side, cudaStreamNonBlocking);
    cudaEvent_t eFork, eJoin;
    cudaEventCreateWithFlags(&eFork, cudaEventDisableTiming);
    cudaEventCreateWithFlags(&eJoin, cudaEventDisableTiming);

    // fork: CSR build is independent of features -> overlap with init+embed
    cudaEventRecord(eFork, 0);
    cudaStreamWaitEvent(side, eFork, 0);

    int Etot = E1 + E2;
    zero_off<<<(N1_C + 1024) / 1024, 1024, 0, side>>>();
    hist_edges<<<(Etot + 255) / 256, 256, 0, side>>>(dst1, E1, dst2, E2);
    scan_offsets<<<2, 1024, 0, side>>>();
    fill_edges<<<(Etot + 255) / 256, 256, 0, side>>>(src1, dst1, E1,
                                                     src2, dst2, E2);
    cudaEventRecord(eJoin, side);

    // main stream: init (weights + fp16 emb) then embed
    init_wemb<<<1024, 256>>>(Wl1, Wr1, Wl2, Wr2, emb);
    embed_ln_relu<<<(N0 * 32 + 255) / 256, 256>>>(x, ln_g, ln_b, N0);

    // join: pulls need both embed output and CSR
    cudaStreamWaitEvent(0, eJoin, 0);

    // layer-1 pull -> A1, GEMM -> h1h (fp16)
    pull_mean<<<(N1_C * 32 + 255) / 256, 256>>>(h0h, off1, adj1, A1, N1_C);
    sage_gemm_tc<2, 1, 0, 1><<<(N1_C + 63) / 64, 128>>>(A1, wt1, bl1,
                                                        nullptr, h1h, N1_C);

    // layer-2 pull -> A2, GEMM -> d_out (fp32)
    pull_mean<<<(N2_C * 32 + 255) / 256, 256>>>(h1h, off2, adj2, A2, N2_C);
    sage_gemm_tc<1, 0, 1, 0><<<(N2_C + 31) / 32, 128>>>(A2, wt2, bl2,
                                                        (float*)d_out, nullptr, N2_C);
}

// round 12
// speedup vs baseline: 2.5051x; 1.0424x over previous
#include <cuda_runtime.h>
#include <cuda_fp16.h>
#include <cstdint>

// ---------------- problem constants (fixed by the dataset) ----------------
#define IN_C   128
#define LEAF   50000
#define N0_MAX 100000
#define W_BAG  16
#define N1_C   25000
#define N2_C   5000
#define E1_MAX 500000
#define E2_MAX 100000

// ---------------- device scratch (allocation-free rule) -------------------
__device__ __half g_embh[(size_t)LEAF * IN_C];    // 12.8 MB fp16 emb table
__device__ __half g_h0h[(size_t)N0_MAX * IN_C];   // 25.6 MB fp16 h0
__device__ __half g_h1h[(size_t)N1_C * IN_C];     //  6.4 MB fp16 h1
__device__ __half g_A1[(size_t)N1_C * 256];       // 12.8 MB fp16 [mean|self] L1
__device__ __half g_A2[(size_t)N2_C * 256];       //  2.6 MB fp16 [mean|self] L2
__device__ int    g_off1[N1_C + 1];
__device__ int    g_off2[N2_C + 1];
__device__ int    g_cur1[N1_C];
__device__ int    g_cur2[N2_C];
__device__ int    g_adj1[E1_MAX];
__device__ int    g_adj2[E2_MAX];
__device__ __half g_Wh1[128 * 256];               // [t][k] combined (Wl|Wr), fp16
__device__ __half g_Wh2[128 * 256];

// ---------------- small asm helpers ----------------------------------------
__device__ __forceinline__ void mma_f16(float* d, const unsigned* a, const unsigned* b) {
    asm volatile(
        "mma.sync.aligned.m16n8k16.row.col.f32.f16.f16.f32 "
        "{%0,%1,%2,%3}, {%4,%5,%6,%7}, {%8,%9}, {%0,%1,%2,%3};"
        : "+f"(d[0]), "+f"(d[1]), "+f"(d[2]), "+f"(d[3])
        : "r"(a[0]), "r"(a[1]), "r"(a[2]), "r"(a[3]), "r"(b[0]), "r"(b[1]));
}
__device__ __forceinline__ void cp16(unsigned smem_dst, const void* gsrc, bool pred) {
    int sz = pred ? 16 : 0;
    asm volatile("cp.async.cg.shared.global [%0], [%1], 16, %2;"
                 :: "r"(smem_dst), "l"(gsrc), "r"(sz));
}
__device__ __forceinline__ void cp_commit() {
    asm volatile("cp.async.commit_group;");
}
__device__ __forceinline__ void cp_wait0() {
    asm volatile("cp.async.wait_group 0;");
}

// 4 halves -> float4 (8B load)
__device__ __forceinline__ float4 ld_half4(const __half* p) {
    uint2 r = __ldg((const uint2*)p);
    __half2 a = *reinterpret_cast<__half2*>(&r.x);
    __half2 b = *reinterpret_cast<__half2*>(&r.y);
    float2 fa = __half22float2(a), fb = __half22float2(b);
    return make_float4(fa.x, fa.y, fb.x, fb.y);
}
// float4 -> 4 halves (8B store)
__device__ __forceinline__ void st_half4(__half* p, float4 v) {
    __half2 a = __floats2half2_rn(v.x, v.y);
    __half2 b = __floats2half2_rn(v.z, v.w);
    uint2 r;
    r.x = *reinterpret_cast<unsigned*>(&a);
    r.y = *reinterpret_cast<unsigned*>(&b);
    *(uint2*)p = r;
}

// ---------------- main-stream init: fp16 weight prep + fp16 emb ------------
__global__ void init_wemb(const float* __restrict__ Wl1, const float* __restrict__ Wr1,
                          const float* __restrict__ Wl2, const float* __restrict__ Wr2,
                          const float* __restrict__ emb) {
    int i  = blockIdx.x * blockDim.x + threadIdx.x;
    int st = gridDim.x * blockDim.x;
    // weights: [t][k] layout (k contiguous) = col-major B for the f16 MMA
    for (int j = i; j < 128 * 256; j += st) {
        int t = j >> 8;
        int k = j & 255;
        float w1 = (k < 128) ? Wl1[t * 128 + k] : Wr1[t * 128 + (k - 128)];
        float w2 = (k < 128) ? Wl2[t * 128 + k] : Wr2[t * 128 + (k - 128)];
        g_Wh1[j] = __float2half(w1);
        g_Wh2[j] = __float2half(w2);
    }
    for (int j = i; j < LEAF * IN_C / 4; j += st) {
        float4 v = __ldg((const float4*)(emb + (size_t)j * 4));
        st_half4(g_embh + (size_t)j * 4, v);
    }
}

// ---------------- side stream: zero CSR offsets -----------------------------
__global__ void zero_off() {
    int i = blockIdx.x * blockDim.x + threadIdx.x;
    if (i <= N1_C) g_off1[i] = 0;
    if (i <= N2_C) g_off2[i] = 0;
}

// ---------------- side stream: histogram (both layers) ----------------------
__global__ void hist_edges(const int* __restrict__ dst1, int E1,
                           const int* __restrict__ dst2, int E2) {
    int i = blockIdx.x * blockDim.x + threadIdx.x;
    if (i < E1) {
        atomicAdd(&g_off1[__ldg(dst1 + i) + 1], 1);
    } else if (i < E1 + E2) {
        atomicAdd(&g_off2[__ldg(dst2 + (i - E1)) + 1], 1);
    }
}

// ---------------- side stream: warp-shuffle prefix scan ---------------------
#define MAXC 25
__global__ __launch_bounds__(1024)
void scan_offsets() {
    int* off = blockIdx.x ? g_off2 : g_off1;
    int* cur = blockIdx.x ? g_cur2 : g_cur1;
    int  n   = blockIdx.x ? N2_C : N1_C;
    __shared__ int wsum[32];

    int t    = threadIdx.x;
    int lane = t & 31;
    int wid  = t >> 5;
    int C  = (n + 1023) >> 10;
    int lo = t * C;
    int hi = min(n, lo + C);
    int cnt = hi - lo; if (cnt < 0) cnt = 0;

    int v[MAXC];
#pragma unroll
    for (int j = 0; j < MAXC; ++j)
        if (j < cnt) v[j] = off[1 + lo + j];

    int s = 0;
#pragma unroll
    for (int j = 0; j < MAXC; ++j)
        if (j < cnt) s += v[j];
    int sOrig = s;

#pragma unroll
    for (int o = 1; o < 32; o <<= 1) {
        int u = __shfl_up_sync(0xffffffffu, s, o);
        if (lane >= o) s += u;
    }
    if (lane == 31) wsum[wid] = s;
    __syncthreads();
    if (wid == 0) {
        int w = wsum[lane];
#pragma unroll
        for (int o = 1; o < 32; o <<= 1) {
            int u = __shfl_up_sync(0xffffffffu, w, o);
            if (lane >= o) w += u;
        }
        wsum[lane] = w;
    }
    __syncthreads();

    int base = (wid ? wsum[wid - 1] : 0) + (s - sOrig);
    int run = base;
#pragma unroll
    for (int j = 0; j < MAXC; ++j) {
        if (j < cnt) {
            cur[lo + j] = run;
            run += v[j];
            off[1 + lo + j] = run;
        }
    }
}

// ---------------- side stream: fill adjacency (both layers) -----------------
__global__ void fill_edges(const int* __restrict__ src1, const int* __restrict__ dst1, int E1,
                           const int* __restrict__ src2, const int* __restrict__ dst2, int E2) {
    int i = blockIdx.x * blockDim.x + threadIdx.x;
    if (i < E1) {
        int d = __ldg(dst1 + i);
        int pos = atomicAdd(&g_cur1[d], 1);
        g_adj1[pos] = __ldg(src1 + i);
    } else if (i < E1 + E2) {
        int e = i - E1;
        int d = __ldg(dst2 + e);
        int pos = atomicAdd(&g_cur2[d], 1);
        g_adj2[pos] = __ldg(src2 + e);
    }
}

// ---------------- embedding bag sum + layernorm + relu (fp16 in/out) -------
__global__ void embed_ln_relu(const int* __restrict__ x, const float* __restrict__ g,
                              const float* __restrict__ b, int N0) {
    int warp = (blockIdx.x * blockDim.x + threadIdx.x) >> 5;
    int lane = threadIdx.x & 31;
    if (warp >= N0) return;

    int idx_l = (lane < W_BAG) ? __ldg(x + (size_t)warp * W_BAG + lane) : 0;

    float4 a0 = make_float4(0.f, 0.f, 0.f, 0.f);
    float4 a1 = make_float4(0.f, 0.f, 0.f, 0.f);
#pragma unroll
    for (int w = 0; w < W_BAG; w += 2) {
        int i0 = __shfl_sync(0xffffffffu, idx_l, w);
        int i1 = __shfl_sync(0xffffffffu, idx_l, w + 1);
        float4 e0 = ld_half4(g_embh + (size_t)i0 * IN_C + lane * 4);
        float4 e1 = ld_half4(g_embh + (size_t)i1 * IN_C + lane * 4);
        a0.x += e0.x; a0.y += e0.y; a0.z += e0.z; a0.w += e0.w;
        a1.x += e1.x; a1.y += e1.y; a1.z += e1.z; a1.w += e1.w;
    }
    float4 acc;
    acc.x = a0.x + a1.x; acc.y = a0.y + a1.y;
    acc.z = a0.z + a1.z; acc.w = a0.w + a1.w;

    float s = acc.x + acc.y + acc.z + acc.w;
#pragma unroll
    for (int o = 16; o; o >>= 1) s += __shfl_xor_sync(0xffffffffu, s, o);
    float mu = s * (1.0f / 128.0f);
    float d0 = acc.x - mu, d1 = acc.y - mu, d2 = acc.z - mu, d3 = acc.w - mu;
    float q = d0 * d0 + d1 * d1 + d2 * d2 + d3 * d3;
#pragma unroll
    for (int o = 16; o; o >>= 1) q += __shfl_xor_sync(0xffffffffu, q, o);
    float rs = rsqrtf(q * (1.0f / 128.0f) + 1e-5f);

    float4 gg = __ldg((const float4*)(g + lane * 4));
    float4 bb = __ldg((const float4*)(b + lane * 4));
    float4 o4;
    o4.x = fmaxf(fmaf(d0 * rs, gg.x, bb.x), 0.f);
    o4.y = fmaxf(fmaf(d1 * rs, gg.y, bb.y), 0.f);
    o4.z = fmaxf(fmaf(d2 * rs, gg.z, bb.z), 0.f);
    o4.w = fmaxf(fmaf(d3 * rs, gg.w, bb.w), 0.f);
    st_half4(g_h0h + (size_t)warp * IN_C + lane * 4, o4);
}

// ---------------- pull aggregation: A[r] = [mean | self] (fp16 out) --------
__global__ void pull_mean(const __half* __restrict__ h, const int* __restrict__ off,
                          const int* __restrict__ adj, __half* __restrict__ A, int n) {
    int warp = (blockIdx.x * blockDim.x + threadIdx.x) >> 5;
    int lane = threadIdx.x & 31;
    if (warp >= n) return;

    int o0 = __ldg(off + warp);
    int o1 = __ldg(off + warp + 1);

    float4 acc0 = make_float4(0.f, 0.f, 0.f, 0.f);
    float4 acc1 = make_float4(0.f, 0.f, 0.f, 0.f);
    int d = o0;
    for (; d + 4 <= o1; d += 4) {
        int s0 = __ldg(adj + d);
        int s1 = __ldg(adj + d + 1);
        int s2 = __ldg(adj + d + 2);
        int s3 = __ldg(adj + d + 3);
        float4 e0 = ld_half4(h + (size_t)s0 * IN_C + lane * 4);
        float4 e1 = ld_half4(h + (size_t)s1 * IN_C + lane * 4);
        float4 e2 = ld_half4(h + (size_t)s2 * IN_C + lane * 4);
        float4 e3 = ld_half4(h + (size_t)s3 * IN_C + lane * 4);
        acc0.x += e0.x + e2.x; acc0.y += e0.y + e2.y;
        acc0.z += e0.z + e2.z; acc0.w += e0.w + e2.w;
        acc1.x += e1.x + e3.x; acc1.y += e1.y + e3.y;
        acc1.z += e1.z + e3.z; acc1.w += e1.w + e3.w;
    }
    for (; d < o1; ++d) {
        int s = __ldg(adj + d);
        float4 e = ld_half4(h + (size_t)s * IN_C + lane * 4);
        acc0.x += e.x; acc0.y += e.y; acc0.z += e.z; acc0.w += e.w;
    }
    float inv = (o1 > o0) ? (1.0f / (float)(o1 - o0)) : 0.0f;
    float4 m;
    m.x = (acc0.x + acc1.x) * inv;
    m.y = (acc0.y + acc1.y) * inv;
    m.z = (acc0.z + acc1.z) * inv;
    m.w = (acc0.w + acc1.w) * inv;
    st_half4(A + (size_t)warp * 256 + lane * 4, m);

    // self copy: raw fp16 bits, no re-rounding
    uint2 raw = __ldg((const uint2*)(h + (size_t)warp * IN_C + lane * 4));
    *(uint2*)(A + (size_t)warp * 256 + 128 + lane * 4) = raw;
}

// ---------------- fp16 tensor-core fused SAGE GEMM --------------------------
// out[n,128] = A[n,0:128] @ Wl^T + bias + A[n,128:256] @ Wr^T (+relu)
// A fp16 [n,256]; W fp16 [t][k] (col-major B). 128 threads = 4 warps (2Mx2N);
// CTA tile (MFRAG*32) x 128; K chunks 32, cp.async double-buffered;
// mma.sync m16n8k16 f16, fp32 accumulate.
template<int MFRAG, int DO_RELU, int WRITE_F32, int WRITE_HALF>
__global__ __launch_bounds__(128)
void sage_gemm_f16(const __half* __restrict__ A, const __half* __restrict__ Wh,
                   const float* __restrict__ bias, float* __restrict__ out,
                   __half* __restrict__ outh, int n) {
    constexpr int TM = MFRAG * 32;

    __shared__ __half As[2][TM][40];    // stride 40 halves: all frag LDS conflict-free
    __shared__ __half Ws[2][128][40];   // [col][k]

    int tid  = threadIdx.x;
    int lane = tid & 31;
    int w    = tid >> 5;
    int g    = lane >> 2;
    int tig  = lane & 3;
    int wm   = w >> 1;
    int wn   = w & 1;
    int row0 = blockIdx.x * TM;

    auto copyA = [&](int c, int buf) {
#pragma unroll
        for (int i = 0; i < TM / 32; ++i) {
            int idx = tid + i * 128;
            int r = idx >> 2, seg = idx & 3;    // 4x 16B segs per 32-half row slice
            const __half* src = A + (size_t)(row0 + r) * 256 + c * 32 + seg * 8;
            cp16((unsigned)__cvta_generic_to_shared(&As[buf][r][seg * 8]),
                 src, (row0 + r) < n);
        }
    };
    auto copyW = [&](int c, int buf) {
#pragma unroll
        for (int i = 0; i < 4; ++i) {
            int idx = tid + i * 128;
            int col = idx >> 2, seg = idx & 3;
            const __half* src = Wh + (size_t)col * 256 + c * 32 + seg * 8;
            cp16((unsigned)__cvta_generic_to_shared(&Ws[buf][col][seg * 8]),
                 src, true);
        }
    };

    float acc[MFRAG][8][4];
#pragma unroll
    for (int mf = 0; mf < MFRAG; ++mf)
#pragma unroll
        for (int nt = 0; nt < 8; ++nt)
#pragma unroll
            for (int q = 0; q < 4; ++q) acc[mf][nt][q] = 0.f;

    copyA(0, 0); copyW(0, 0); cp_commit();

#pragma unroll
    for (int c = 0; c < 8; ++c) {
        int buf = c & 1;
        cp_wait0();
        __syncthreads();
        if (c < 7) { copyA(c + 1, buf ^ 1); copyW(c + 1, buf ^ 1); cp_commit(); }

#pragma unroll
        for (int ks = 0; ks < 2; ++ks) {
            int kk = ks * 16;
            unsigned a[MFRAG][4];
#pragma unroll
            for (int mf = 0; mf < MFRAG; ++mf) {
                int r0 = wm * MFRAG * 16 + mf * 16 + g;
                a[mf][0] = *(const unsigned*)&As[buf][r0][kk + tig * 2];
                a[mf][1] = *(const unsigned*)&As[buf][r0 + 8][kk + tig * 2];
                a[mf][2] = *(const unsigned*)&As[buf][r0][kk + tig * 2 + 8];
                a[mf][3] = *(const unsigned*)&As[buf][r0 + 8][kk + tig * 2 + 8];
            }
            unsigned b[8][2];
#pragma unroll
            for (int nt = 0; nt < 8; ++nt) {
                int col = wn * 64 + nt * 8 + g;
                b[nt][0] = *(const unsigned*)&Ws[buf][col][kk + tig * 2];
                b[nt][1] = *(const unsigned*)&Ws[buf][col][kk + tig * 2 + 8];
            }
#pragma unroll
            for (int mf = 0; mf < MFRAG; ++mf)
#pragma unroll
                for (int nt = 0; nt < 8; ++nt)
                    mma_f16(acc[mf][nt], a[mf], b[nt]);
        }
    }

    // epilogue: bias (+relu), fp32 and/or fp16 stores
#pragma unroll
    for (int mf = 0; mf < MFRAG; ++mf) {
        int rbase = row0 + wm * MFRAG * 16 + mf * 16 + g;
#pragma unroll
        for (int nt = 0; nt < 8; ++nt) {
            int cl = wn * 64 + nt * 8 + tig * 2;
            float2 bb = __ldg((const float2*)(bias + cl));
            float2 o0, o1;
            o0.x = acc[mf][nt][0] + bb.x;
            o0.y = acc[mf][nt][1] + bb.y;
            o1.x = acc[mf][nt][2] + bb.x;
            o1.y = acc[mf][nt][3] + bb.y;
            if (DO_RELU) {
                o0.x = fmaxf(o0.x, 0.f); o0.y = fmaxf(o0.y, 0.f);
                o1.x = fmaxf(o1.x, 0.f); o1.y = fmaxf(o1.y, 0.f);
            }
            if (rbase < n) {
                if (WRITE_F32)
                    *(float2*)(out + (size_t)rbase * 128 + cl) = o0;
                if (WRITE_HALF)
                    *(__half2*)(outh + (size_t)rbase * 128 + cl) =
                        __floats2half2_rn(o0.x, o0.y);
            }
            if (rbase + 8 < n) {
                if (WRITE_F32)
                    *(float2*)(out + (size_t)(rbase + 8) * 128 + cl) = o1;
                if (WRITE_HALF)
                    *(__half2*)(outh + (size_t)(rbase + 8) * 128 + cl) =
                        __floats2half2_rn(o1.x, o1.y);
            }
        }
    }
}

// ---------------- host launcher --------------------------------------------
extern "C" void kernel_launch(void* const* d_in, const int* in_sizes, int n_in,
                              void* d_out, int out_size) {
    int ix = 0, is1 = 1, id1 = 2, is2 = 3, id2 = 4;
    int iemb, ig, ib, iwl1, ibl1, iwr1, iwl2, ibl2, iwr2;
    if (n_in >= 16) {
        iemb = 7; ig = 8; ib = 9; iwl1 = 10; ibl1 = 11; iwr1 = 12;
        iwl2 = 13; ibl2 = 14; iwr2 = 15;
    } else {
        iemb = 5; ig = 6; ib = 7; iwl1 = 8; ibl1 = 9; iwr1 = 10;
        iwl2 = 11; ibl2 = 12; iwr2 = 13;
    }

    const int*   x    = (const int*)d_in[ix];
    const int*   src1 = (const int*)d_in[is1];
    const int*   dst1 = (const int*)d_in[id1];
    const int*   src2 = (const int*)d_in[is2];
    const int*   dst2 = (const int*)d_in[id2];
    const float* emb  = (const float*)d_in[iemb];
    const float* ln_g = (const float*)d_in[ig];
    const float* ln_b = (const float*)d_in[ib];
    const float* Wl1  = (const float*)d_in[iwl1];
    const float* bl1  = (const float*)d_in[ibl1];
    const float* Wr1  = (const float*)d_in[iwr1];
    const float* Wl2  = (const float*)d_in[iwl2];
    const float* bl2  = (const float*)d_in[ibl2];
    const float* Wr2  = (const float*)d_in[iwr2];

    int N0 = in_sizes[ix] / W_BAG;
    int E1 = in_sizes[is1]; if (E1 > E1_MAX) E1 = E1_MAX;
    int E2 = in_sizes[is2]; if (E2 > E2_MAX) E2 = E2_MAX;

    __half *h0h, *h1h, *A1, *A2, *wh1, *wh2;
    int *off1, *off2, *adj1, *adj2;
    cudaGetSymbolAddress((void**)&h0h,  g_h0h);
    cudaGetSymbolAddress((void**)&h1h,  g_h1h);
    cudaGetSymbolAddress((void**)&A1,   g_A1);
    cudaGetSymbolAddress((void**)&A2,   g_A2);
    cudaGetSymbolAddress((void**)&wh1,  g_Wh1);
    cudaGetSymbolAddress((void**)&wh2,  g_Wh2);
    cudaGetSymbolAddress((void**)&off1, g_off1);
    cudaGetSymbolAddress((void**)&off2, g_off2);
    cudaGetSymbolAddress((void**)&adj1, g_adj1);
    cudaGetSymbolAddress((void**)&adj2, g_adj2);

    // side stream + fork/join events
    cudaStream_t side;
    cudaStreamCreateWithFlags(&side, cudaStreamNonBlocking);
    cudaEvent_t eFork, eJoin;
    cudaEventCreateWithFlags(&eFork, cudaEventDisableTiming);
    cudaEventCreateWithFlags(&eJoin, cudaEventDisableTiming);

    // fork: CSR build overlaps init+embed
    cudaEventRecord(eFork, 0);
    cudaStreamWaitEvent(side, eFork, 0);

    int Etot = E1 + E2;
    zero_off<<<(N1_C + 1024) / 1024, 1024, 0, side>>>();
    hist_edges<<<(Etot + 255) / 256, 256, 0, side>>>(dst1, E1, dst2, E2);
    scan_offsets<<<2, 1024, 0, side>>>();
    fill_edges<<<(Etot + 255) / 256, 256, 0, side>>>(src1, dst1, E1,
                                                     src2, dst2, E2);
    cudaEventRecord(eJoin, side);

    // main stream: init (fp16 weights + fp16 emb) then embed
    init_wemb<<<1024, 256>>>(Wl1, Wr1, Wl2, Wr2, emb);
    embed_ln_relu<<<(N0 * 32 + 255) / 256, 256>>>(x, ln_g, ln_b, N0);

    // join: pulls need both embed output and CSR
    cudaStreamWaitEvent(0, eJoin, 0);

    // layer-1 pull -> A1 (fp16), GEMM -> h1h (fp16)
    pull_mean<<<(N1_C * 32 + 255) / 256, 256>>>(h0h, off1, adj1, A1, N1_C);
    sage_gemm_f16<2, 1, 0, 1><<<(N1_C + 63) / 64, 128>>>(A1, wh1, bl1,
                                                         nullptr, h1h, N1_C);

    // layer-2 pull -> A2 (fp16), GEMM -> d_out (fp32)
    pull_mean<<<(N2_C * 32 + 255) / 256, 256>>>(h1h, off2, adj2, A2, N2_C);
    sage_gemm_f16<1, 0, 1, 0><<<(N2_C + 31) / 32, 128>>>(A2, wh2, bl2,
                                                         (float*)d_out, nullptr, N2_C);
}